// round 11
// baseline (speedup 1.0000x reference)
#include <cuda_runtime.h>
#include <cuda_fp16.h>

#define NN 50000
#define EE 800000
#define DD 128
#define GG 64
#define CC 8

#define SCAN_TB 256
#define SCAN_BLOCKS ((NN + SCAN_TB - 1) / SCAN_TB)   // 196

#define SSTR 136
// B hi/lo resident (2*64 rows) + A hi double-buffer (2*8 rows)
#define GEMM_SMEM_UINTS ((64 * 2 + 2 * 8) * SSTR)
#define GEMM_SMEM_BYTES (GEMM_SMEM_UINTS * 4)        // 78336

// ---------------- static scratch ----------------
__device__ __half g_xw[NN * 256];       // [N, 256] fp16: cols 0-127 rel0, 128-255 rel1
__device__ float g_agg[NN * DD];
__device__ float g_invd0[NN];
__device__ float g_invd1[NN];
__device__ int   g_deg0[NN];
__device__ int   g_deg1[NN];
__device__ int   g_ptr0[NN + 1];
__device__ int   g_ptr1[NN + 1];
__device__ int   g_cur0[NN];
__device__ int   g_cur1[NN];
__device__ int2  g_ce0[EE];
__device__ int2  g_ce1[EE];
__device__ int   g_bsum[2][SCAN_BLOCKS];
// pre-split W as packed fp16 pairs: [mat(layer*2+rel)][k2 (=k/2)][c], uint = {half(k), half(k+1)}
__device__ unsigned g_whi[2 * 2 * (DD / 2) * DD];
__device__ unsigned g_wlo[2 * 2 * (DD / 2) * DD];
__device__ float g_pooled[GG * DD];
__device__ int   g_counts[GG];
__device__ int   g_offsets[GG + 1];

// ---------------- helpers ----------------
__device__ __forceinline__ unsigned packh2(__half a, __half b) {
    __half2 h = __halves2half2(a, b);
    return *reinterpret_cast<unsigned*>(&h);
}
__device__ __forceinline__ void mma_f16(float* c, const unsigned* a, const unsigned* b) {
    asm volatile(
        "mma.sync.aligned.m16n8k16.row.col.f32.f16.f16.f32 "
        "{%0,%1,%2,%3}, {%4,%5,%6,%7}, {%8,%9}, {%0,%1,%2,%3};"
        : "+f"(c[0]), "+f"(c[1]), "+f"(c[2]), "+f"(c[3])
        : "r"(a[0]), "r"(a[1]), "r"(a[2]), "r"(a[3]), "r"(b[0]), "r"(b[1]));
}

// ---------------- setup ----------------
__global__ void zero_all() {
    int i = blockIdx.x * blockDim.x + threadIdx.x;
    if (i < NN) { g_deg0[i] = 0; g_deg1[i] = 0; }
    if (i < GG) g_counts[i] = 0;
    if (i < GG * DD) g_pooled[i] = 0.0f;
}

// degree histograms for both relations + batch counts, one kernel
__global__ void hist_both(const int* __restrict__ ei, const int* __restrict__ batch) {
    int t = blockIdx.x * blockDim.x + threadIdx.x;
    if (t < EE)                 atomicAdd(&g_deg0[ei[EE + t]], 1);
    else if (t < 2 * EE)        atomicAdd(&g_deg1[ei[3 * EE + (t - EE)]], 1);
    else if (t < 2 * EE + NN)   atomicAdd(&g_counts[batch[t - 2 * EE]], 1);
}

// split all weights into fp16 hi + lo pairs (once per call)
__global__ void wsplit(const float* __restrict__ W) {
    int i = blockIdx.x * blockDim.x + threadIdx.x;   // over 2*2*64*128 = 65536
    if (i < 2 * 2 * (DD / 2) * DD) {
        int mat = i / ((DD / 2) * DD);
        int rem = i % ((DD / 2) * DD);
        int k2 = rem / DD, c = rem % DD;
        const float* Wm = W + mat * DD * DD;
        float w0 = Wm[(2 * k2) * DD + c];
        float w1 = Wm[(2 * k2 + 1) * DD + c];
        __half h0 = __float2half_rn(w0);
        __half h1 = __float2half_rn(w1);
        __half l0 = __float2half_rn(w0 - __half2float(h0));
        __half l1 = __float2half_rn(w1 - __half2float(h1));
        g_whi[i] = packh2(h0, h1);
        g_wlo[i] = packh2(l0, l1);
    }
}

// block-exclusive prescan; also computes invd (fused)
__global__ void scan_p1() {
    int rel = blockIdx.y;
    const int* __restrict__ cnt = rel ? g_deg1 : g_deg0;
    int* __restrict__ ptr = rel ? g_ptr1 : g_ptr0;
    float* __restrict__ invd = rel ? g_invd1 : g_invd0;
    int i = blockIdx.x * SCAN_TB + threadIdx.x;
    int v = (i < NN) ? cnt[i] : 0;
    if (i < NN) invd[i] = rsqrtf((float)(v + 1));
    int lane = threadIdx.x & 31, w = threadIdx.x >> 5;
    int incl = v;
    #pragma unroll
    for (int o = 1; o < 32; o <<= 1) {
        int t = __shfl_up_sync(0xffffffffu, incl, o);
        if (lane >= o) incl += t;
    }
    __shared__ int wsum[8];
    if (lane == 31) wsum[w] = incl;
    __syncthreads();
    if (w == 0) {
        int s = (lane < 8) ? wsum[lane] : 0;
        #pragma unroll
        for (int o = 1; o < 8; o <<= 1) {
            int t = __shfl_up_sync(0xffffffffu, s, o);
            if (lane >= o) s += t;
        }
        if (lane < 8) wsum[lane] = s;
    }
    __syncthreads();
    int base = (w > 0) ? wsum[w - 1] : 0;
    if (i < NN) ptr[i] = base + incl - v;
    if (threadIdx.x == SCAN_TB - 1) g_bsum[rel][blockIdx.x] = base + incl;
}

__global__ void scan_p2() {
    int rel = blockIdx.x;
    int tid = threadIdx.x;
    int v = (tid < SCAN_BLOCKS) ? g_bsum[rel][tid] : 0;
    int lane = tid & 31, w = tid >> 5;
    int incl = v;
    #pragma unroll
    for (int o = 1; o < 32; o <<= 1) {
        int t = __shfl_up_sync(0xffffffffu, incl, o);
        if (lane >= o) incl += t;
    }
    __shared__ int wsum[8];
    if (lane == 31) wsum[w] = incl;
    __syncthreads();
    if (w == 0) {
        int s = (lane < 8) ? wsum[lane] : 0;
        #pragma unroll
        for (int o = 1; o < 8; o <<= 1) {
            int t = __shfl_up_sync(0xffffffffu, s, o);
            if (lane >= o) s += t;
        }
        if (lane < 8) wsum[lane] = s;
    }
    __syncthreads();
    int base = (w > 0) ? wsum[w - 1] : 0;
    if (tid < SCAN_BLOCKS) g_bsum[rel][tid] = base + incl - v;
}

__global__ void scan_p3() {
    int rel = blockIdx.y;
    int* __restrict__ ptr = rel ? g_ptr1 : g_ptr0;
    int* __restrict__ cur = rel ? g_cur1 : g_cur0;
    int i = blockIdx.x * SCAN_TB + threadIdx.x;
    if (i < NN) {
        int p = ptr[i] + g_bsum[rel][blockIdx.x];
        ptr[i] = p; cur[i] = p;
    }
    if (i == 0) ptr[NN] = EE;
}

__global__ void csr_fill_both(const int* __restrict__ ei) {
    int t = blockIdx.x * blockDim.x + threadIdx.x;
    if (t < EE) {
        int s = ei[t], d = ei[EE + t];
        int slot = atomicAdd(&g_cur0[d], 1);
        int2 p; p.x = s; p.y = __float_as_int(g_invd0[s] * g_invd0[d]);
        g_ce0[slot] = p;
    } else if (t < 2 * EE) {
        int e = t - EE;
        int s = ei[2 * EE + e], d = ei[3 * EE + e];
        int slot = atomicAdd(&g_cur1[d], 1);
        int2 p; p.x = s; p.y = __float_as_int(g_invd1[s] * g_invd1[d]);
        g_ce1[slot] = p;
    }
}

// ---------------- tensor-core GEMM (2-term split: Ah*(Bh+Bl), B resident, A double-buffered) ----------------
// 256 threads, grid (391, 2). One __syncthreads per 16-K chunk.
template <bool RELU>
__global__ void __launch_bounds__(256, 2)
gemm_tc(const float* __restrict__ A, const unsigned* __restrict__ Whi,
        const unsigned* __restrict__ Wlo, __half* __restrict__ out) {
    extern __shared__ unsigned dynsm[];
    unsigned* sBhi = dynsm;                       // [64][SSTR]
    unsigned* sBlo = sBhi + 64 * SSTR;            // [64][SSTR]
    unsigned* sAhi = sBlo + 64 * SSTR;            // [2][8][SSTR]

    const int rel = blockIdx.y;
    const unsigned* Bh = Whi + rel * (DD / 2) * DD;
    const unsigned* Bl = Wlo + rel * (DD / 2) * DD;
    const int rowBase = blockIdx.x * 128;
    const int tid = threadIdx.x;
    const int warp = tid >> 5, lane = tid & 31;
    const int wm = warp >> 2, wn = warp & 3;
    const int lrow = lane >> 2;     // 0..7
    const int lk = lane & 3;        // pair index 0..3

    float acc[4][4][4];
    #pragma unroll
    for (int i = 0; i < 4; ++i)
        #pragma unroll
        for (int j = 0; j < 4; ++j)
            #pragma unroll
            for (int q = 0; q < 4; ++q) acc[i][j][q] = 0.0f;

    // ---- load whole B (hi+lo) into smem once ----
    #pragma unroll
    for (int i = 0; i < 8; ++i) {
        int idx = tid + i * 256;               // 0..2047 uint4 slots
        int k2 = idx >> 5, c = (idx & 31) * 4;
        *reinterpret_cast<uint4*>(&sBhi[k2 * SSTR + c]) =
            *reinterpret_cast<const uint4*>(Bh + k2 * DD + c);
        *reinterpret_cast<uint4*>(&sBlo[k2 * SSTR + c]) =
            *reinterpret_cast<const uint4*>(Bl + k2 * DD + c);
    }

    const int alr = tid >> 1;            // A row 0..127
    const int alk = (tid & 1) * 8;       // k offset 0 or 8
    const int ap2 = (tid & 1) * 4;       // pair-row offset 0 or 4
    const int agr = rowBase + alr;
    const bool arow_ok = (agr < NN);
    const float* aBase = A + (size_t)agr * DD + alk;

    // ---- prologue: load + convert chunk 0 into buffer 0 ----
    {
        float4 v0 = make_float4(0.f, 0.f, 0.f, 0.f), v1 = v0;
        if (arow_ok) {
            v0 = *reinterpret_cast<const float4*>(aBase);
            v1 = *reinterpret_cast<const float4*>(aBase + 4);
        }
        if (RELU) {
            v0.x = fmaxf(v0.x, 0.f); v0.y = fmaxf(v0.y, 0.f);
            v0.z = fmaxf(v0.z, 0.f); v0.w = fmaxf(v0.w, 0.f);
            v1.x = fmaxf(v1.x, 0.f); v1.y = fmaxf(v1.y, 0.f);
            v1.z = fmaxf(v1.z, 0.f); v1.w = fmaxf(v1.w, 0.f);
        }
        sAhi[(ap2 + 0) * SSTR + alr] = packh2(__float2half_rn(v0.x), __float2half_rn(v0.y));
        sAhi[(ap2 + 1) * SSTR + alr] = packh2(__float2half_rn(v0.z), __float2half_rn(v0.w));
        sAhi[(ap2 + 2) * SSTR + alr] = packh2(__float2half_rn(v1.x), __float2half_rn(v1.y));
        sAhi[(ap2 + 3) * SSTR + alr] = packh2(__float2half_rn(v1.z), __float2half_rn(v1.w));
    }
    __syncthreads();

    // ---- mainloop: 8 chunks, prefetch next A while computing ----
    #pragma unroll
    for (int c = 0; c < 8; ++c) {
        const int cur = c & 1;
        unsigned* cAhi = sAhi + cur * 8 * SSTR;
        unsigned* nAhi = sAhi + (cur ^ 1) * 8 * SSTR;

        // prefetch next chunk (LDG issued before LDS/MMA)
        float4 v0 = make_float4(0.f, 0.f, 0.f, 0.f), v1 = v0;
        if (c < 7 && arow_ok) {
            const float* ap = aBase + (c + 1) * 16;
            v0 = *reinterpret_cast<const float4*>(ap);
            v1 = *reinterpret_cast<const float4*>(ap + 4);
        }

        // fragments
        const int kb = c * 8;
        unsigned ua[4][4];
        unsigned ubh[4][2], ubl[4][2];
        #pragma unroll
        for (int mt = 0; mt < 4; ++mt) {
            int rm = wm * 64 + mt * 16 + lrow;
            ua[mt][0] = cAhi[lk * SSTR + rm];
            ua[mt][1] = cAhi[lk * SSTR + rm + 8];
            ua[mt][2] = cAhi[(lk + 4) * SSTR + rm];
            ua[mt][3] = cAhi[(lk + 4) * SSTR + rm + 8];
        }
        #pragma unroll
        for (int nt = 0; nt < 4; ++nt) {
            int cn = wn * 32 + nt * 8 + lrow;
            ubh[nt][0] = sBhi[(kb + lk) * SSTR + cn];
            ubh[nt][1] = sBhi[(kb + lk + 4) * SSTR + cn];
            ubl[nt][0] = sBlo[(kb + lk) * SSTR + cn];
            ubl[nt][1] = sBlo[(kb + lk + 4) * SSTR + cn];
        }
        // hi x hi
        #pragma unroll
        for (int mt = 0; mt < 4; ++mt)
            #pragma unroll
            for (int nt = 0; nt < 4; ++nt)
                mma_f16(acc[mt][nt], ua[mt], ubh[nt]);
        // hi x lo
        #pragma unroll
        for (int mt = 0; mt < 4; ++mt)
            #pragma unroll
            for (int nt = 0; nt < 4; ++nt)
                mma_f16(acc[mt][nt], ua[mt], ubl[nt]);

        // convert + store prefetched chunk into the other buffer
        if (c < 7) {
            if (RELU) {
                v0.x = fmaxf(v0.x, 0.f); v0.y = fmaxf(v0.y, 0.f);
                v0.z = fmaxf(v0.z, 0.f); v0.w = fmaxf(v0.w, 0.f);
                v1.x = fmaxf(v1.x, 0.f); v1.y = fmaxf(v1.y, 0.f);
                v1.z = fmaxf(v1.z, 0.f); v1.w = fmaxf(v1.w, 0.f);
            }
            nAhi[(ap2 + 0) * SSTR + alr] = packh2(__float2half_rn(v0.x), __float2half_rn(v0.y));
            nAhi[(ap2 + 1) * SSTR + alr] = packh2(__float2half_rn(v0.z), __float2half_rn(v0.w));
            nAhi[(ap2 + 2) * SSTR + alr] = packh2(__float2half_rn(v1.x), __float2half_rn(v1.y));
            nAhi[(ap2 + 3) * SSTR + alr] = packh2(__float2half_rn(v1.z), __float2half_rn(v1.w));
        }
        __syncthreads();
    }

    #pragma unroll
    for (int mt = 0; mt < 4; ++mt) {
        int r0 = rowBase + wm * 64 + mt * 16 + lrow;
        #pragma unroll
        for (int nt = 0; nt < 4; ++nt) {
            int cn = rel * 128 + wn * 32 + nt * 8 + 2 * lk;
            if (r0 < NN)
                *reinterpret_cast<__half2*>(out + (size_t)r0 * 256 + cn) =
                    __floats2half2_rn(acc[mt][nt][0], acc[mt][nt][1]);
            if (r0 + 8 < NN)
                *reinterpret_cast<__half2*>(out + (size_t)(r0 + 8) * 256 + cn) =
                    __floats2half2_rn(acc[mt][nt][2], acc[mt][nt][3]);
        }
    }
}

// ---------------- fused aggregation (CSR gather, fp16 source) ----------------
__device__ __forceinline__ float4 ldh4(const __half* p) {
    uint2 u = *reinterpret_cast<const uint2*>(p);
    float2 fa = __half22float2(*reinterpret_cast<__half2*>(&u.x));
    float2 fb = __half22float2(*reinterpret_cast<__half2*>(&u.y));
    return make_float4(fa.x, fa.y, fb.x, fb.y);
}

__global__ void gather_both(const __half* __restrict__ xw,
                            const float* __restrict__ b_l,
                            float* __restrict__ agg) {
    int t = blockIdx.x * blockDim.x + threadIdx.x;
    int i = t >> 5;
    int lane = t & 31;
    if (i >= NN) return;
    int c4 = lane * 4;

    float s0 = g_invd0[i]; s0 *= s0;
    float s1 = g_invd1[i]; s1 *= s1;
    float4 v0 = ldh4(xw + (size_t)i * 256 + c4);
    float4 v1 = ldh4(xw + (size_t)i * 256 + 128 + c4);
    float4 acc;
    acc.x = fmaf(v0.x, s0, v1.x * s1) + b_l[c4 + 0] + b_l[DD + c4 + 0];
    acc.y = fmaf(v0.y, s0, v1.y * s1) + b_l[c4 + 1] + b_l[DD + c4 + 1];
    acc.z = fmaf(v0.z, s0, v1.z * s1) + b_l[c4 + 2] + b_l[DD + c4 + 2];
    acc.w = fmaf(v0.w, s0, v1.w * s1) + b_l[c4 + 3] + b_l[DD + c4 + 3];

    {
        int b0 = g_ptr0[i], e0 = g_ptr0[i + 1];
        int tt = b0;
        for (; tt + 1 < e0; tt += 2) {
            int2 pA = g_ce0[tt], pB = g_ce0[tt + 1];
            float wA = __int_as_float(pA.y), wB = __int_as_float(pB.y);
            float4 vA = ldh4(xw + (size_t)pA.x * 256 + c4);
            float4 vB = ldh4(xw + (size_t)pB.x * 256 + c4);
            acc.x = fmaf(wA, vA.x, fmaf(wB, vB.x, acc.x));
            acc.y = fmaf(wA, vA.y, fmaf(wB, vB.y, acc.y));
            acc.z = fmaf(wA, vA.z, fmaf(wB, vB.z, acc.z));
            acc.w = fmaf(wA, vA.w, fmaf(wB, vB.w, acc.w));
        }
        if (tt < e0) {
            int2 p = g_ce0[tt];
            float w = __int_as_float(p.y);
            float4 v = ldh4(xw + (size_t)p.x * 256 + c4);
            acc.x = fmaf(w, v.x, acc.x); acc.y = fmaf(w, v.y, acc.y);
            acc.z = fmaf(w, v.z, acc.z); acc.w = fmaf(w, v.w, acc.w);
        }
    }
    {
        int b1 = g_ptr1[i], e1 = g_ptr1[i + 1];
        int tt = b1;
        for (; tt + 1 < e1; tt += 2) {
            int2 pA = g_ce1[tt], pB = g_ce1[tt + 1];
            float wA = __int_as_float(pA.y), wB = __int_as_float(pB.y);
            float4 vA = ldh4(xw + (size_t)pA.x * 256 + 128 + c4);
            float4 vB = ldh4(xw + (size_t)pB.x * 256 + 128 + c4);
            acc.x = fmaf(wA, vA.x, fmaf(wB, vB.x, acc.x));
            acc.y = fmaf(wA, vA.y, fmaf(wB, vB.y, acc.y));
            acc.z = fmaf(wA, vA.z, fmaf(wB, vB.z, acc.z));
            acc.w = fmaf(wA, vA.w, fmaf(wB, vB.w, acc.w));
        }
        if (tt < e1) {
            int2 p = g_ce1[tt];
            float w = __int_as_float(p.y);
            float4 v = ldh4(xw + (size_t)p.x * 256 + 128 + c4);
            acc.x = fmaf(w, v.x, acc.x); acc.y = fmaf(w, v.y, acc.y);
            acc.z = fmaf(w, v.z, acc.z); acc.w = fmaf(w, v.w, acc.w);
        }
    }
    *reinterpret_cast<float4*>(agg + (size_t)i * DD + c4) = acc;
}

// ---------------- pooling + classifier ----------------
__global__ void scan64() {
    if (threadIdx.x == 0) {
        int acc = 0;
        for (int g = 0; g < GG; ++g) { g_offsets[g] = acc; acc += g_counts[g]; }
        g_offsets[GG] = acc;
    }
}

__global__ void pool_partial(const float* __restrict__ h) {
    int g = blockIdx.x;
    int chunk = blockIdx.y;
    int d = threadIdx.x;
    int start = g_offsets[g], end = g_offsets[g + 1];
    int n = end - start;
    int per = (n + (int)gridDim.y - 1) / (int)gridDim.y;
    int s = start + chunk * per;
    int e = min(end, s + per);
    float acc = 0.0f;
    for (int i = s; i < e; ++i) acc += h[(size_t)i * DD + d];
    if (s < e) atomicAdd(&g_pooled[g * DD + d], acc);
}

__global__ void final_linear(const float* __restrict__ lin_w,
                             const float* __restrict__ lin_b,
                             float* __restrict__ out) {
    int t = threadIdx.x;
    int g = t >> 3, c = t & 7;
    float cnt = (float)max(g_counts[g], 1);
    float acc = 0.0f;
    #pragma unroll 16
    for (int d = 0; d < DD; ++d) acc += g_pooled[g * DD + d] * lin_w[d * CC + c];
    out[g * CC + c] = acc / cnt + lin_b[c];
}

// ---------------- launch ----------------
extern "C" void kernel_launch(void* const* d_in, const int* in_sizes, int n_in,
                              void* d_out, int out_size) {
    const float* x     = (const float*)d_in[0];
    const float* W     = (const float*)d_in[1];
    const float* b     = (const float*)d_in[2];
    const float* lin_w = (const float*)d_in[3];
    const float* lin_b = (const float*)d_in[4];
    const int*   ei    = (const int*)d_in[5];
    const int*   batch = (const int*)d_in[6];
    float* out = (float*)d_out;

    __half* xw; float* agg;
    unsigned *whi, *wlo;
    cudaGetSymbolAddress((void**)&xw,  g_xw);
    cudaGetSymbolAddress((void**)&agg, g_agg);
    cudaGetSymbolAddress((void**)&whi, g_whi);
    cudaGetSymbolAddress((void**)&wlo, g_wlo);

    cudaFuncSetAttribute(gemm_tc<false>, cudaFuncAttributeMaxDynamicSharedMemorySize,
                         GEMM_SMEM_BYTES);
    cudaFuncSetAttribute(gemm_tc<true>, cudaFuncAttributeMaxDynamicSharedMemorySize,
                         GEMM_SMEM_BYTES);

    const int TB = 256;
    int nodeBlocks  = (NN + TB - 1) / TB;
    int histBlocks  = (2 * EE + NN + TB - 1) / TB;
    int edge2Blocks = (2 * EE + TB - 1) / TB;
    int warpBlocks  = (NN * 32 + TB - 1) / TB;
    int wsplitBlocks = (2 * 2 * (DD / 2) * DD + TB - 1) / TB;
    dim3 gemmGrid((NN + 127) / 128, 2);
    dim3 scanGrid(SCAN_BLOCKS, 2);

    const int WMAT = (DD / 2) * DD;   // packed uints per weight matrix

    zero_all<<<nodeBlocks, TB>>>();                 // 0
    hist_both<<<histBlocks, TB>>>(ei, batch);       // 1
    wsplit<<<wsplitBlocks, TB>>>(W);                // 2
    gemm_tc<false><<<gemmGrid, 256, GEMM_SMEM_BYTES>>>(x, whi, wlo, xw);   // 3 (profiled)
    scan_p1<<<scanGrid, SCAN_TB>>>();               // 4
    scan_p2<<<2, 256>>>();                          // 5
    scan_p3<<<scanGrid, SCAN_TB>>>();               // 6
    csr_fill_both<<<edge2Blocks, TB>>>(ei);         // 7
    gather_both<<<warpBlocks, TB>>>(xw, b + 0 * 2 * DD, agg);              // 8

    gemm_tc<true><<<gemmGrid, 256, GEMM_SMEM_BYTES>>>(agg, whi + 2 * WMAT,
                                                      wlo + 2 * WMAT, xw); // 9
    gather_both<<<warpBlocks, TB>>>(xw, b + 1 * 2 * DD, agg);              // 10

    scan64<<<1, 32>>>();
    dim3 pg(GG, 8);
    pool_partial<<<pg, DD>>>(agg);
    final_linear<<<1, GG * CC>>>(lin_w, lin_b, out);
}

// round 12
// speedup vs baseline: 1.2775x; 1.2775x over previous
#include <cuda_runtime.h>
#include <cuda_fp16.h>

#define NN 50000
#define EE 800000
#define DD 128
#define GG 64
#define CC 8

#define SCAN_TB 256
#define SCAN_BLOCKS ((NN + SCAN_TB - 1) / SCAN_TB)   // 196

#define SSTR 136
// B hi/lo resident (2*64 rows) + A hi/lo double-buffer (2*2*8 rows)
#define GEMM_SMEM_UINTS ((64 * 2 + 2 * 2 * 8) * SSTR)
#define GEMM_SMEM_BYTES (GEMM_SMEM_UINTS * 4)        // 87040

#define GEMM_BLOCKS (((NN + 127) / 128) * 2)         // 782
#define CSR_BLOCKS ((2 * EE + 255) / 256)            // 6250

// ---------------- static scratch ----------------
__device__ __half g_xw[NN * 256];       // [N, 256] fp16: cols 0-127 rel0, 128-255 rel1
__device__ float g_agg[NN * DD];
__device__ float g_invd0[NN];
__device__ float g_invd1[NN];
__device__ int   g_deg0[NN];
__device__ int   g_deg1[NN];
__device__ int   g_ptr0[NN + 1];
__device__ int   g_ptr1[NN + 1];
__device__ int   g_cur0[NN];
__device__ int   g_cur1[NN];
__device__ int2  g_ce0[EE];
__device__ int2  g_ce1[EE];
__device__ int   g_bsum[2][SCAN_BLOCKS];
// pre-split W as packed fp16 pairs: [mat(layer*2+rel)][k2 (=k/2)][c], uint = {half(k), half(k+1)}
__device__ unsigned g_whi[2 * 2 * (DD / 2) * DD];
__device__ unsigned g_wlo[2 * 2 * (DD / 2) * DD];
__device__ float g_pooled[GG * DD];
__device__ int   g_counts[GG];
__device__ int   g_offsets[GG + 1];

// ---------------- helpers ----------------
__device__ __forceinline__ unsigned packh2(__half a, __half b) {
    __half2 h = __halves2half2(a, b);
    return *reinterpret_cast<unsigned*>(&h);
}
__device__ __forceinline__ void mma_f16(float* c, const unsigned* a, const unsigned* b) {
    asm volatile(
        "mma.sync.aligned.m16n8k16.row.col.f32.f16.f16.f32 "
        "{%0,%1,%2,%3}, {%4,%5,%6,%7}, {%8,%9}, {%0,%1,%2,%3};"
        : "+f"(c[0]), "+f"(c[1]), "+f"(c[2]), "+f"(c[3])
        : "r"(a[0]), "r"(a[1]), "r"(a[2]), "r"(a[3]), "r"(b[0]), "r"(b[1]));
}

// ---------------- setup ----------------
// zero counters + split W into fp16 hi/lo pairs (both dependency-free)
__global__ void zero_wsplit(const float* __restrict__ W) {
    int i = blockIdx.x * blockDim.x + threadIdx.x;   // 256*256 = 65536 threads
    if (i < NN) { g_deg0[i] = 0; g_deg1[i] = 0; }
    if (i < GG) g_counts[i] = 0;
    if (i < GG * DD) g_pooled[i] = 0.0f;
    if (i < 2 * 2 * (DD / 2) * DD) {
        int mat = i / ((DD / 2) * DD);
        int rem = i % ((DD / 2) * DD);
        int k2 = rem / DD, c = rem % DD;
        const float* Wm = W + mat * DD * DD;
        float w0 = Wm[(2 * k2) * DD + c];
        float w1 = Wm[(2 * k2 + 1) * DD + c];
        __half h0 = __float2half_rn(w0);
        __half h1 = __float2half_rn(w1);
        __half l0 = __float2half_rn(w0 - __half2float(h0));
        __half l1 = __float2half_rn(w1 - __half2float(h1));
        g_whi[i] = packh2(h0, h1);
        g_wlo[i] = packh2(l0, l1);
    }
}

// degree histograms for both relations + batch counts, one kernel
__global__ void hist_both(const int* __restrict__ ei, const int* __restrict__ batch) {
    int t = blockIdx.x * blockDim.x + threadIdx.x;
    if (t < EE)                 atomicAdd(&g_deg0[ei[EE + t]], 1);
    else if (t < 2 * EE)        atomicAdd(&g_deg1[ei[3 * EE + (t - EE)]], 1);
    else if (t < 2 * EE + NN)   atomicAdd(&g_counts[batch[t - 2 * EE]], 1);
}

// block-exclusive prescan; also computes invd (fused)
__global__ void scan_p1() {
    int rel = blockIdx.y;
    const int* __restrict__ cnt = rel ? g_deg1 : g_deg0;
    int* __restrict__ ptr = rel ? g_ptr1 : g_ptr0;
    float* __restrict__ invd = rel ? g_invd1 : g_invd0;
    int i = blockIdx.x * SCAN_TB + threadIdx.x;
    int v = (i < NN) ? cnt[i] : 0;
    if (i < NN) invd[i] = rsqrtf((float)(v + 1));
    int lane = threadIdx.x & 31, w = threadIdx.x >> 5;
    int incl = v;
    #pragma unroll
    for (int o = 1; o < 32; o <<= 1) {
        int t = __shfl_up_sync(0xffffffffu, incl, o);
        if (lane >= o) incl += t;
    }
    __shared__ int wsum[8];
    if (lane == 31) wsum[w] = incl;
    __syncthreads();
    if (w == 0) {
        int s = (lane < 8) ? wsum[lane] : 0;
        #pragma unroll
        for (int o = 1; o < 8; o <<= 1) {
            int t = __shfl_up_sync(0xffffffffu, s, o);
            if (lane >= o) s += t;
        }
        if (lane < 8) wsum[lane] = s;
    }
    __syncthreads();
    int base = (w > 0) ? wsum[w - 1] : 0;
    if (i < NN) ptr[i] = base + incl - v;
    if (threadIdx.x == SCAN_TB - 1) g_bsum[rel][blockIdx.x] = base + incl;
}

__global__ void scan_p2() {
    int rel = blockIdx.x;
    int tid = threadIdx.x;
    int v = (tid < SCAN_BLOCKS) ? g_bsum[rel][tid] : 0;
    int lane = tid & 31, w = tid >> 5;
    int incl = v;
    #pragma unroll
    for (int o = 1; o < 32; o <<= 1) {
        int t = __shfl_up_sync(0xffffffffu, incl, o);
        if (lane >= o) incl += t;
    }
    __shared__ int wsum[8];
    if (lane == 31) wsum[w] = incl;
    __syncthreads();
    if (w == 0) {
        int s = (lane < 8) ? wsum[lane] : 0;
        #pragma unroll
        for (int o = 1; o < 8; o <<= 1) {
            int t = __shfl_up_sync(0xffffffffu, s, o);
            if (lane >= o) s += t;
        }
        if (lane < 8) wsum[lane] = s;
    }
    __syncthreads();
    int base = (w > 0) ? wsum[w - 1] : 0;
    if (tid < SCAN_BLOCKS) g_bsum[rel][tid] = base + incl - v;
}

__global__ void scan_p3() {
    int rel = blockIdx.y;
    int* __restrict__ ptr = rel ? g_ptr1 : g_ptr0;
    int* __restrict__ cur = rel ? g_cur1 : g_cur0;
    int i = blockIdx.x * SCAN_TB + threadIdx.x;
    if (i < NN) {
        int p = ptr[i] + g_bsum[rel][blockIdx.x];
        ptr[i] = p; cur[i] = p;
    }
    if (i == 0) ptr[NN] = EE;
}

// ---------------- csr fill body (device) ----------------
__device__ __forceinline__ void csr_fill_body(int t, const int* __restrict__ ei) {
    if (t < EE) {
        int s = ei[t], d = ei[EE + t];
        int slot = atomicAdd(&g_cur0[d], 1);
        int2 p; p.x = s; p.y = __float_as_int(g_invd0[s] * g_invd0[d]);
        g_ce0[slot] = p;
    } else if (t < 2 * EE) {
        int e = t - EE;
        int s = ei[2 * EE + e], d = ei[3 * EE + e];
        int slot = atomicAdd(&g_cur1[d], 1);
        int2 p; p.x = s; p.y = __float_as_int(g_invd1[s] * g_invd1[d]);
        g_ce1[slot] = p;
    }
}

// ---------------- gemm body (device, round-10 3-term fp16 split) ----------------
template <bool RELU>
__device__ __forceinline__ void gemm_body(
    int rel, int rowBlk, const float* __restrict__ A,
    const unsigned* __restrict__ Whi, const unsigned* __restrict__ Wlo,
    __half* __restrict__ out, unsigned* dynsm
) {
    unsigned* sBhi = dynsm;                       // [64][SSTR]
    unsigned* sBlo = sBhi + 64 * SSTR;            // [64][SSTR]
    unsigned* sAhi = sBlo + 64 * SSTR;            // [2][8][SSTR]
    unsigned* sAlo = sAhi + 2 * 8 * SSTR;         // [2][8][SSTR]

    const unsigned* Bh = Whi + rel * (DD / 2) * DD;
    const unsigned* Bl = Wlo + rel * (DD / 2) * DD;
    const int rowBase = rowBlk * 128;
    const int tid = threadIdx.x;
    const int warp = tid >> 5, lane = tid & 31;
    const int wm = warp >> 2, wn = warp & 3;
    const int lrow = lane >> 2;     // 0..7
    const int lk = lane & 3;        // pair index 0..3

    float acc[4][4][4];
    #pragma unroll
    for (int i = 0; i < 4; ++i)
        #pragma unroll
        for (int j = 0; j < 4; ++j)
            #pragma unroll
            for (int q = 0; q < 4; ++q) acc[i][j][q] = 0.0f;

    // ---- load whole B (hi+lo) into smem once ----
    #pragma unroll
    for (int i = 0; i < 8; ++i) {
        int idx = tid + i * 256;               // 0..2047 uint4 slots
        int k2 = idx >> 5, c = (idx & 31) * 4;
        *reinterpret_cast<uint4*>(&sBhi[k2 * SSTR + c]) =
            *reinterpret_cast<const uint4*>(Bh + k2 * DD + c);
        *reinterpret_cast<uint4*>(&sBlo[k2 * SSTR + c]) =
            *reinterpret_cast<const uint4*>(Bl + k2 * DD + c);
    }

    const int alr = tid >> 1;            // A row 0..127
    const int alk = (tid & 1) * 8;       // k offset 0 or 8
    const int ap2 = (tid & 1) * 4;       // pair-row offset 0 or 4
    const int agr = rowBase + alr;
    const bool arow_ok = (agr < NN);
    const float* aBase = A + (size_t)agr * DD + alk;

    // ---- prologue: load + split chunk 0 into buffer 0 ----
    {
        float4 v0 = make_float4(0.f, 0.f, 0.f, 0.f), v1 = v0;
        if (arow_ok) {
            v0 = *reinterpret_cast<const float4*>(aBase);
            v1 = *reinterpret_cast<const float4*>(aBase + 4);
        }
        if (RELU) {
            v0.x = fmaxf(v0.x, 0.f); v0.y = fmaxf(v0.y, 0.f);
            v0.z = fmaxf(v0.z, 0.f); v0.w = fmaxf(v0.w, 0.f);
            v1.x = fmaxf(v1.x, 0.f); v1.y = fmaxf(v1.y, 0.f);
            v1.z = fmaxf(v1.z, 0.f); v1.w = fmaxf(v1.w, 0.f);
        }
        float va[8] = {v0.x, v0.y, v0.z, v0.w, v1.x, v1.y, v1.z, v1.w};
        #pragma unroll
        for (int p = 0; p < 4; ++p) {
            __half h0 = __float2half_rn(va[2 * p]);
            __half h1 = __float2half_rn(va[2 * p + 1]);
            __half l0 = __float2half_rn(va[2 * p] - __half2float(h0));
            __half l1 = __float2half_rn(va[2 * p + 1] - __half2float(h1));
            sAhi[(ap2 + p) * SSTR + alr] = packh2(h0, h1);
            sAlo[(ap2 + p) * SSTR + alr] = packh2(l0, l1);
        }
    }
    __syncthreads();

    // ---- mainloop: 8 chunks, prefetch next A while computing ----
    #pragma unroll
    for (int c = 0; c < 8; ++c) {
        const int cur = c & 1;
        unsigned* cAhi = sAhi + cur * 8 * SSTR;
        unsigned* cAlo = sAlo + cur * 8 * SSTR;
        unsigned* nAhi = sAhi + (cur ^ 1) * 8 * SSTR;
        unsigned* nAlo = sAlo + (cur ^ 1) * 8 * SSTR;

        // prefetch next chunk (LDG issued before LDS/MMA)
        float4 v0 = make_float4(0.f, 0.f, 0.f, 0.f), v1 = v0;
        if (c < 7 && arow_ok) {
            const float* ap = aBase + (c + 1) * 16;
            v0 = *reinterpret_cast<const float4*>(ap);
            v1 = *reinterpret_cast<const float4*>(ap + 4);
        }

        // fragments
        const int kb = c * 8;
        unsigned ua[4][4];
        unsigned ubh[4][2], ubl[4][2];
        #pragma unroll
        for (int mt = 0; mt < 4; ++mt) {
            int rm = wm * 64 + mt * 16 + lrow;
            ua[mt][0] = cAhi[lk * SSTR + rm];
            ua[mt][1] = cAhi[lk * SSTR + rm + 8];
            ua[mt][2] = cAhi[(lk + 4) * SSTR + rm];
            ua[mt][3] = cAhi[(lk + 4) * SSTR + rm + 8];
        }
        #pragma unroll
        for (int nt = 0; nt < 4; ++nt) {
            int cn = wn * 32 + nt * 8 + lrow;
            ubh[nt][0] = sBhi[(kb + lk) * SSTR + cn];
            ubh[nt][1] = sBhi[(kb + lk + 4) * SSTR + cn];
            ubl[nt][0] = sBlo[(kb + lk) * SSTR + cn];
            ubl[nt][1] = sBlo[(kb + lk + 4) * SSTR + cn];
        }
        // hi x hi
        #pragma unroll
        for (int mt = 0; mt < 4; ++mt)
            #pragma unroll
            for (int nt = 0; nt < 4; ++nt)
                mma_f16(acc[mt][nt], ua[mt], ubh[nt]);
        // hi x lo
        #pragma unroll
        for (int mt = 0; mt < 4; ++mt)
            #pragma unroll
            for (int nt = 0; nt < 4; ++nt)
                mma_f16(acc[mt][nt], ua[mt], ubl[nt]);
        // lo x hi
        #pragma unroll
        for (int mt = 0; mt < 4; ++mt) {
            int rm = wm * 64 + mt * 16 + lrow;
            ua[mt][0] = cAlo[lk * SSTR + rm];
            ua[mt][1] = cAlo[lk * SSTR + rm + 8];
            ua[mt][2] = cAlo[(lk + 4) * SSTR + rm];
            ua[mt][3] = cAlo[(lk + 4) * SSTR + rm + 8];
        }
        #pragma unroll
        for (int mt = 0; mt < 4; ++mt)
            #pragma unroll
            for (int nt = 0; nt < 4; ++nt)
                mma_f16(acc[mt][nt], ua[mt], ubh[nt]);

        // split + store prefetched chunk into the other buffer
        if (c < 7) {
            if (RELU) {
                v0.x = fmaxf(v0.x, 0.f); v0.y = fmaxf(v0.y, 0.f);
                v0.z = fmaxf(v0.z, 0.f); v0.w = fmaxf(v0.w, 0.f);
                v1.x = fmaxf(v1.x, 0.f); v1.y = fmaxf(v1.y, 0.f);
                v1.z = fmaxf(v1.z, 0.f); v1.w = fmaxf(v1.w, 0.f);
            }
            float va[8] = {v0.x, v0.y, v0.z, v0.w, v1.x, v1.y, v1.z, v1.w};
            #pragma unroll
            for (int p = 0; p < 4; ++p) {
                __half h0 = __float2half_rn(va[2 * p]);
                __half h1 = __float2half_rn(va[2 * p + 1]);
                __half l0 = __float2half_rn(va[2 * p] - __half2float(h0));
                __half l1 = __float2half_rn(va[2 * p + 1] - __half2float(h1));
                nAhi[(ap2 + p) * SSTR + alr] = packh2(h0, h1);
                nAlo[(ap2 + p) * SSTR + alr] = packh2(l0, l1);
            }
        }
        __syncthreads();
    }

    #pragma unroll
    for (int mt = 0; mt < 4; ++mt) {
        int r0 = rowBase + wm * 64 + mt * 16 + lrow;
        #pragma unroll
        for (int nt = 0; nt < 4; ++nt) {
            int cn = rel * 128 + wn * 32 + nt * 8 + 2 * lk;
            if (r0 < NN)
                *reinterpret_cast<__half2*>(out + (size_t)r0 * 256 + cn) =
                    __floats2half2_rn(acc[mt][nt][0], acc[mt][nt][1]);
            if (r0 + 8 < NN)
                *reinterpret_cast<__half2*>(out + (size_t)(r0 + 8) * 256 + cn) =
                    __floats2half2_rn(acc[mt][nt][2], acc[mt][nt][3]);
        }
    }
}

// ---------------- layer-0 GEMM + csr_fill (fused; independent work overlapped) ----------------
__global__ void __launch_bounds__(256, 2)
gemm0_csr(const float* __restrict__ A, const unsigned* __restrict__ Whi,
          const unsigned* __restrict__ Wlo, __half* __restrict__ out,
          const int* __restrict__ ei) {
    extern __shared__ unsigned dynsm[];
    int bid = blockIdx.x;
    if (bid < GEMM_BLOCKS) {
        int rel = bid / (GEMM_BLOCKS / 2);
        int rowBlk = bid % (GEMM_BLOCKS / 2);
        gemm_body<false>(rel, rowBlk, A, Whi, Wlo, out, dynsm);
    } else {
        int t = (bid - GEMM_BLOCKS) * 256 + threadIdx.x;
        csr_fill_body(t, ei);
    }
}

// ---------------- layer-1 GEMM (plain) ----------------
__global__ void __launch_bounds__(256, 2)
gemm_l1(const float* __restrict__ A, const unsigned* __restrict__ Whi,
        const unsigned* __restrict__ Wlo, __half* __restrict__ out) {
    extern __shared__ unsigned dynsm[];
    gemm_body<true>(blockIdx.y, blockIdx.x, A, Whi, Wlo, out, dynsm);
}

// ---------------- fused aggregation (CSR gather, fp16 source) ----------------
__device__ __forceinline__ float4 ldh4(const __half* p) {
    uint2 u = *reinterpret_cast<const uint2*>(p);
    float2 fa = __half22float2(*reinterpret_cast<__half2*>(&u.x));
    float2 fb = __half22float2(*reinterpret_cast<__half2*>(&u.y));
    return make_float4(fa.x, fa.y, fb.x, fb.y);
}

__global__ void gather_both(const __half* __restrict__ xw,
                            const float* __restrict__ b_l,
                            float* __restrict__ agg) {
    int t = blockIdx.x * blockDim.x + threadIdx.x;
    int i = t >> 5;
    int lane = t & 31;
    if (i >= NN) return;
    int c4 = lane * 4;

    float s0 = g_invd0[i]; s0 *= s0;
    float s1 = g_invd1[i]; s1 *= s1;
    float4 v0 = ldh4(xw + (size_t)i * 256 + c4);
    float4 v1 = ldh4(xw + (size_t)i * 256 + 128 + c4);
    float4 acc;
    acc.x = fmaf(v0.x, s0, v1.x * s1) + b_l[c4 + 0] + b_l[DD + c4 + 0];
    acc.y = fmaf(v0.y, s0, v1.y * s1) + b_l[c4 + 1] + b_l[DD + c4 + 1];
    acc.z = fmaf(v0.z, s0, v1.z * s1) + b_l[c4 + 2] + b_l[DD + c4 + 2];
    acc.w = fmaf(v0.w, s0, v1.w * s1) + b_l[c4 + 3] + b_l[DD + c4 + 3];

    {
        int b0 = g_ptr0[i], e0 = g_ptr0[i + 1];
        int tt = b0;
        for (; tt + 1 < e0; tt += 2) {
            int2 pA = g_ce0[tt], pB = g_ce0[tt + 1];
            float wA = __int_as_float(pA.y), wB = __int_as_float(pB.y);
            float4 vA = ldh4(xw + (size_t)pA.x * 256 + c4);
            float4 vB = ldh4(xw + (size_t)pB.x * 256 + c4);
            acc.x = fmaf(wA, vA.x, fmaf(wB, vB.x, acc.x));
            acc.y = fmaf(wA, vA.y, fmaf(wB, vB.y, acc.y));
            acc.z = fmaf(wA, vA.z, fmaf(wB, vB.z, acc.z));
            acc.w = fmaf(wA, vA.w, fmaf(wB, vB.w, acc.w));
        }
        if (tt < e0) {
            int2 p = g_ce0[tt];
            float w = __int_as_float(p.y);
            float4 v = ldh4(xw + (size_t)p.x * 256 + c4);
            acc.x = fmaf(w, v.x, acc.x); acc.y = fmaf(w, v.y, acc.y);
            acc.z = fmaf(w, v.z, acc.z); acc.w = fmaf(w, v.w, acc.w);
        }
    }
    {
        int b1 = g_ptr1[i], e1 = g_ptr1[i + 1];
        int tt = b1;
        for (; tt + 1 < e1; tt += 2) {
            int2 pA = g_ce1[tt], pB = g_ce1[tt + 1];
            float wA = __int_as_float(pA.y), wB = __int_as_float(pB.y);
            float4 vA = ldh4(xw + (size_t)pA.x * 256 + 128 + c4);
            float4 vB = ldh4(xw + (size_t)pB.x * 256 + 128 + c4);
            acc.x = fmaf(wA, vA.x, fmaf(wB, vB.x, acc.x));
            acc.y = fmaf(wA, vA.y, fmaf(wB, vB.y, acc.y));
            acc.z = fmaf(wA, vA.z, fmaf(wB, vB.z, acc.z));
            acc.w = fmaf(wA, vA.w, fmaf(wB, vB.w, acc.w));
        }
        if (tt < e1) {
            int2 p = g_ce1[tt];
            float w = __int_as_float(p.y);
            float4 v = ldh4(xw + (size_t)p.x * 256 + 128 + c4);
            acc.x = fmaf(w, v.x, acc.x); acc.y = fmaf(w, v.y, acc.y);
            acc.z = fmaf(w, v.z, acc.z); acc.w = fmaf(w, v.w, acc.w);
        }
    }
    *reinterpret_cast<float4*>(agg + (size_t)i * DD + c4) = acc;
}

// ---------------- pooling + classifier ----------------
__global__ void scan64() {
    if (threadIdx.x == 0) {
        int acc = 0;
        for (int g = 0; g < GG; ++g) { g_offsets[g] = acc; acc += g_counts[g]; }
        g_offsets[GG] = acc;
    }
}

__global__ void pool_partial(const float* __restrict__ h) {
    int g = blockIdx.x;
    int chunk = blockIdx.y;
    int d = threadIdx.x;
    int start = g_offsets[g], end = g_offsets[g + 1];
    int n = end - start;
    int per = (n + (int)gridDim.y - 1) / (int)gridDim.y;
    int s = start + chunk * per;
    int e = min(end, s + per);
    float acc = 0.0f;
    for (int i = s; i < e; ++i) acc += h[(size_t)i * DD + d];
    if (s < e) atomicAdd(&g_pooled[g * DD + d], acc);
}

__global__ void final_linear(const float* __restrict__ lin_w,
                             const float* __restrict__ lin_b,
                             float* __restrict__ out) {
    int t = threadIdx.x;
    int g = t >> 3, c = t & 7;
    float cnt = (float)max(g_counts[g], 1);
    float acc = 0.0f;
    #pragma unroll 16
    for (int d = 0; d < DD; ++d) acc += g_pooled[g * DD + d] * lin_w[d * CC + c];
    out[g * CC + c] = acc / cnt + lin_b[c];
}

// ---------------- launch ----------------
extern "C" void kernel_launch(void* const* d_in, const int* in_sizes, int n_in,
                              void* d_out, int out_size) {
    const float* x     = (const float*)d_in[0];
    const float* W     = (const float*)d_in[1];
    const float* b     = (const float*)d_in[2];
    const float* lin_w = (const float*)d_in[3];
    const float* lin_b = (const float*)d_in[4];
    const int*   ei    = (const int*)d_in[5];
    const int*   batch = (const int*)d_in[6];
    float* out = (float*)d_out;

    __half* xw; float* agg;
    unsigned *whi, *wlo;
    cudaGetSymbolAddress((void**)&xw,  g_xw);
    cudaGetSymbolAddress((void**)&agg, g_agg);
    cudaGetSymbolAddress((void**)&whi, g_whi);
    cudaGetSymbolAddress((void**)&wlo, g_wlo);

    cudaFuncSetAttribute(gemm0_csr, cudaFuncAttributeMaxDynamicSharedMemorySize,
                         GEMM_SMEM_BYTES);
    cudaFuncSetAttribute(gemm_l1, cudaFuncAttributeMaxDynamicSharedMemorySize,
                         GEMM_SMEM_BYTES);

    const int TB = 256;
    int nodeBlocks  = (NN + TB - 1) / TB;
    int histBlocks  = (2 * EE + NN + TB - 1) / TB;
    int warpBlocks  = (NN * 32 + TB - 1) / TB;
    dim3 gemmGrid((NN + 127) / 128, 2);
    dim3 scanGrid(SCAN_BLOCKS, 2);

    const int WMAT = (DD / 2) * DD;   // packed uints per weight matrix

    zero_wsplit<<<256, TB>>>(W);                    // 0
    hist_both<<<histBlocks, TB>>>(ei, batch);       // 1
    scan_p1<<<scanGrid, SCAN_TB>>>();               // 2
    scan_p2<<<2, 256>>>();                          // 3
    scan_p3<<<scanGrid, SCAN_TB>>>();               // 4
    // layer-0 GEMM fused with csr_fill (independent; overlap on-chip)
    gemm0_csr<<<GEMM_BLOCKS + CSR_BLOCKS, 256, GEMM_SMEM_BYTES>>>(x, whi, wlo, xw, ei); // 5
    gather_both<<<warpBlocks, TB>>>(xw, b + 0 * 2 * DD, agg);              // 6

    gemm_l1<<<gemmGrid, 256, GEMM_SMEM_BYTES>>>(agg, whi + 2 * WMAT,
                                                wlo + 2 * WMAT, xw);       // 7
    gather_both<<<warpBlocks, TB>>>(xw, b + 1 * 2 * DD, agg);              // 8

    scan64<<<1, 32>>>();
    dim3 pg(GG, 8);
    pool_partial<<<pg, DD>>>(agg);
    final_linear<<<1, GG * CC>>>(lin_w, lin_b, out);
}

// round 13
// speedup vs baseline: 1.3278x; 1.0394x over previous
#include <cuda_runtime.h>
#include <cuda_fp16.h>

#define NN 50000
#define EE 800000
#define DD 128
#define GG 64
#define CC 8

#define SCAN_TB 256
#define SCAN_BLOCKS ((NN + SCAN_TB - 1) / SCAN_TB)   // 196

#define SSTR 136
// B hi/lo resident (2*64 rows) + A hi/lo double-buffer (2*2*16 rows)
#define GEMM_SMEM_UINTS ((64 * 2 + 2 * 2 * 16) * SSTR)
#define GEMM_SMEM_BYTES (GEMM_SMEM_UINTS * 4)        // 104448

// ---------------- static scratch ----------------
__device__ __half g_xw[NN * 256];       // [N, 256] fp16: cols 0-127 rel0, 128-255 rel1
__device__ float g_agg[NN * DD];
__device__ float g_invd0[NN];
__device__ float g_invd1[NN];
__device__ int   g_deg0[NN];
__device__ int   g_deg1[NN];
__device__ int   g_ptr0[NN + 1];
__device__ int   g_ptr1[NN + 1];
__device__ int   g_cur0[NN];
__device__ int   g_cur1[NN];
__device__ int2  g_ce0[EE];
__device__ int2  g_ce1[EE];
__device__ int   g_bsum[2][SCAN_BLOCKS];
// pre-split W as packed fp16 pairs: [mat(layer*2+rel)][k2 (=k/2)][c], uint = {half(k), half(k+1)}
__device__ unsigned g_whi[2 * 2 * (DD / 2) * DD];
__device__ unsigned g_wlo[2 * 2 * (DD / 2) * DD];
__device__ float g_pooled[GG * DD];
__device__ int   g_counts[GG];
__device__ int   g_offsets[GG + 1];

// ---------------- helpers ----------------
__device__ __forceinline__ unsigned packh2(__half a, __half b) {
    __half2 h = __halves2half2(a, b);
    return *reinterpret_cast<unsigned*>(&h);
}
__device__ __forceinline__ void mma_f16(float* c, const unsigned* a, const unsigned* b) {
    asm volatile(
        "mma.sync.aligned.m16n8k16.row.col.f32.f16.f16.f32 "
        "{%0,%1,%2,%3}, {%4,%5,%6,%7}, {%8,%9}, {%0,%1,%2,%3};"
        : "+f"(c[0]), "+f"(c[1]), "+f"(c[2]), "+f"(c[3])
        : "r"(a[0]), "r"(a[1]), "r"(a[2]), "r"(a[3]), "r"(b[0]), "r"(b[1]));
}

// ---------------- setup ----------------
// zero counters + split W into fp16 hi/lo pairs (both dependency-free)
__global__ void zero_wsplit(const float* __restrict__ W) {
    int i = blockIdx.x * blockDim.x + threadIdx.x;   // 256*256 = 65536 threads
    if (i < NN) { g_deg0[i] = 0; g_deg1[i] = 0; }
    if (i < GG) g_counts[i] = 0;
    if (i < GG * DD) g_pooled[i] = 0.0f;
    if (i < 2 * 2 * (DD / 2) * DD) {
        int mat = i / ((DD / 2) * DD);
        int rem = i % ((DD / 2) * DD);
        int k2 = rem / DD, c = rem % DD;
        const float* Wm = W + mat * DD * DD;
        float w0 = Wm[(2 * k2) * DD + c];
        float w1 = Wm[(2 * k2 + 1) * DD + c];
        __half h0 = __float2half_rn(w0);
        __half h1 = __float2half_rn(w1);
        __half l0 = __float2half_rn(w0 - __half2float(h0));
        __half l1 = __float2half_rn(w1 - __half2float(h1));
        g_whi[i] = packh2(h0, h1);
        g_wlo[i] = packh2(l0, l1);
    }
}

// degree histograms for both relations + batch counts, one kernel
__global__ void hist_both(const int* __restrict__ ei, const int* __restrict__ batch) {
    int t = blockIdx.x * blockDim.x + threadIdx.x;
    if (t < EE)                 atomicAdd(&g_deg0[ei[EE + t]], 1);
    else if (t < 2 * EE)        atomicAdd(&g_deg1[ei[3 * EE + (t - EE)]], 1);
    else if (t < 2 * EE + NN)   atomicAdd(&g_counts[batch[t - 2 * EE]], 1);
}

// block-exclusive prescan; also computes invd (fused)
__global__ void scan_p1() {
    int rel = blockIdx.y;
    const int* __restrict__ cnt = rel ? g_deg1 : g_deg0;
    int* __restrict__ ptr = rel ? g_ptr1 : g_ptr0;
    float* __restrict__ invd = rel ? g_invd1 : g_invd0;
    int i = blockIdx.x * SCAN_TB + threadIdx.x;
    int v = (i < NN) ? cnt[i] : 0;
    if (i < NN) invd[i] = rsqrtf((float)(v + 1));
    int lane = threadIdx.x & 31, w = threadIdx.x >> 5;
    int incl = v;
    #pragma unroll
    for (int o = 1; o < 32; o <<= 1) {
        int t = __shfl_up_sync(0xffffffffu, incl, o);
        if (lane >= o) incl += t;
    }
    __shared__ int wsum[8];
    if (lane == 31) wsum[w] = incl;
    __syncthreads();
    if (w == 0) {
        int s = (lane < 8) ? wsum[lane] : 0;
        #pragma unroll
        for (int o = 1; o < 8; o <<= 1) {
            int t = __shfl_up_sync(0xffffffffu, s, o);
            if (lane >= o) s += t;
        }
        if (lane < 8) wsum[lane] = s;
    }
    __syncthreads();
    int base = (w > 0) ? wsum[w - 1] : 0;
    if (i < NN) ptr[i] = base + incl - v;
    if (threadIdx.x == SCAN_TB - 1) g_bsum[rel][blockIdx.x] = base + incl;
}

__global__ void scan_p2() {
    int rel = blockIdx.x;
    int tid = threadIdx.x;
    int v = (tid < SCAN_BLOCKS) ? g_bsum[rel][tid] : 0;
    int lane = tid & 31, w = tid >> 5;
    int incl = v;
    #pragma unroll
    for (int o = 1; o < 32; o <<= 1) {
        int t = __shfl_up_sync(0xffffffffu, incl, o);
        if (lane >= o) incl += t;
    }
    __shared__ int wsum[8];
    if (lane == 31) wsum[w] = incl;
    __syncthreads();
    if (w == 0) {
        int s = (lane < 8) ? wsum[lane] : 0;
        #pragma unroll
        for (int o = 1; o < 8; o <<= 1) {
            int t = __shfl_up_sync(0xffffffffu, s, o);
            if (lane >= o) s += t;
        }
        if (lane < 8) wsum[lane] = s;
    }
    __syncthreads();
    int base = (w > 0) ? wsum[w - 1] : 0;
    if (tid < SCAN_BLOCKS) g_bsum[rel][tid] = base + incl - v;
}

__global__ void scan_p3() {
    int rel = blockIdx.y;
    int* __restrict__ ptr = rel ? g_ptr1 : g_ptr0;
    int* __restrict__ cur = rel ? g_cur1 : g_cur0;
    int i = blockIdx.x * SCAN_TB + threadIdx.x;
    if (i < NN) {
        int p = ptr[i] + g_bsum[rel][blockIdx.x];
        ptr[i] = p; cur[i] = p;
    }
    if (i == 0) ptr[NN] = EE;
}

__global__ void csr_fill_both(const int* __restrict__ ei) {
    int t = blockIdx.x * blockDim.x + threadIdx.x;
    if (t < EE) {
        int s = ei[t], d = ei[EE + t];
        int slot = atomicAdd(&g_cur0[d], 1);
        int2 p; p.x = s; p.y = __float_as_int(g_invd0[s] * g_invd0[d]);
        g_ce0[slot] = p;
    } else if (t < 2 * EE) {
        int e = t - EE;
        int s = ei[2 * EE + e], d = ei[3 * EE + e];
        int slot = atomicAdd(&g_cur1[d], 1);
        int2 p; p.x = s; p.y = __float_as_int(g_invd1[s] * g_invd1[d]);
        g_ce1[slot] = p;
    }
}

// ---------------- tensor-core GEMM (3-term fp16 split, B resident, A double-buffered, BK=32) ----------------
// 256 threads, grid (391, 2). One __syncthreads per 32-K chunk (4 total).
template <bool RELU>
__global__ void __launch_bounds__(256, 2)
gemm_tc(const float* __restrict__ A, const unsigned* __restrict__ Whi,
        const unsigned* __restrict__ Wlo, __half* __restrict__ out) {
    extern __shared__ unsigned dynsm[];
    unsigned* sBhi = dynsm;                       // [64][SSTR]
    unsigned* sBlo = sBhi + 64 * SSTR;            // [64][SSTR]
    unsigned* sAhi = sBlo + 64 * SSTR;            // [2][16][SSTR]
    unsigned* sAlo = sAhi + 2 * 16 * SSTR;        // [2][16][SSTR]

    const int rel = blockIdx.y;
    const unsigned* Bh = Whi + rel * (DD / 2) * DD;
    const unsigned* Bl = Wlo + rel * (DD / 2) * DD;
    const int rowBase = blockIdx.x * 128;
    const int tid = threadIdx.x;
    const int warp = tid >> 5, lane = tid & 31;
    const int wm = warp >> 2, wn = warp & 3;
    const int lrow = lane >> 2;     // 0..7
    const int lk = lane & 3;        // pair index 0..3

    float acc[4][4][4];
    #pragma unroll
    for (int i = 0; i < 4; ++i)
        #pragma unroll
        for (int j = 0; j < 4; ++j)
            #pragma unroll
            for (int q = 0; q < 4; ++q) acc[i][j][q] = 0.0f;

    // ---- load whole B (hi+lo) into smem once ----
    #pragma unroll
    for (int i = 0; i < 8; ++i) {
        int idx = tid + i * 256;               // 0..2047 uint4 slots
        int k2 = idx >> 5, c = (idx & 31) * 4;
        *reinterpret_cast<uint4*>(&sBhi[k2 * SSTR + c]) =
            *reinterpret_cast<const uint4*>(Bh + k2 * DD + c);
        *reinterpret_cast<uint4*>(&sBlo[k2 * SSTR + c]) =
            *reinterpret_cast<const uint4*>(Bl + k2 * DD + c);
    }

    const int alr = tid >> 1;            // A row 0..127
    const int alk = (tid & 1) * 8;       // k offset 0 or 8 within each 16-k half
    const int ap2 = (tid & 1) * 4;       // pair-row offset 0 or 4
    const int agr = rowBase + alr;
    const bool arow_ok = (agr < NN);
    const float* aBase = A + (size_t)agr * DD + alk;

    // per-thread split+store of a 32-k chunk (4 float4 held in v[])
    auto split_store = [&](unsigned* dAhi, unsigned* dAlo,
                           float4 v0, float4 v1, float4 v2, float4 v3) {
        float va[16] = {v0.x, v0.y, v0.z, v0.w, v1.x, v1.y, v1.z, v1.w,
                        v2.x, v2.y, v2.z, v2.w, v3.x, v3.y, v3.z, v3.w};
        #pragma unroll
        for (int h = 0; h < 2; ++h) {          // 16-k half: rows h*8 + ap2 + p
            #pragma unroll
            for (int p = 0; p < 4; ++p) {
                float a0 = va[h * 8 + 2 * p];
                float a1 = va[h * 8 + 2 * p + 1];
                if (RELU) { a0 = fmaxf(a0, 0.f); a1 = fmaxf(a1, 0.f); }
                __half h0 = __float2half_rn(a0);
                __half h1 = __float2half_rn(a1);
                __half l0 = __float2half_rn(a0 - __half2float(h0));
                __half l1 = __float2half_rn(a1 - __half2float(h1));
                dAhi[(h * 8 + ap2 + p) * SSTR + alr] = packh2(h0, h1);
                dAlo[(h * 8 + ap2 + p) * SSTR + alr] = packh2(l0, l1);
            }
        }
    };

    // ---- prologue: load + split chunk 0 (k 0..31) into buffer 0 ----
    {
        float4 v0 = make_float4(0.f, 0.f, 0.f, 0.f), v1 = v0, v2 = v0, v3 = v0;
        if (arow_ok) {
            v0 = *reinterpret_cast<const float4*>(aBase);
            v1 = *reinterpret_cast<const float4*>(aBase + 4);
            v2 = *reinterpret_cast<const float4*>(aBase + 16);
            v3 = *reinterpret_cast<const float4*>(aBase + 20);
        }
        split_store(sAhi, sAlo, v0, v1, v2, v3);
    }
    __syncthreads();

    // ---- mainloop: 4 chunks of 32 k; prefetch next while computing ----
    #pragma unroll
    for (int it = 0; it < 4; ++it) {
        const int cur = it & 1;
        unsigned* cAhi = sAhi + cur * 16 * SSTR;
        unsigned* cAlo = sAlo + cur * 16 * SSTR;
        unsigned* nAhi = sAhi + (cur ^ 1) * 16 * SSTR;
        unsigned* nAlo = sAlo + (cur ^ 1) * 16 * SSTR;

        // prefetch next chunk (LDG issued before LDS/MMA)
        float4 v0 = make_float4(0.f, 0.f, 0.f, 0.f), v1 = v0, v2 = v0, v3 = v0;
        if (it < 3 && arow_ok) {
            const float* ap = aBase + (it + 1) * 32;
            v0 = *reinterpret_cast<const float4*>(ap);
            v1 = *reinterpret_cast<const float4*>(ap + 4);
            v2 = *reinterpret_cast<const float4*>(ap + 16);
            v3 = *reinterpret_cast<const float4*>(ap + 20);
        }

        // two 16-K sub-chunks between syncs
        #pragma unroll
        for (int sub = 0; sub < 2; ++sub) {
            const int s8 = sub * 8;                  // k2-row group in A buffer
            const int kb = it * 16 + sub * 8;        // k2-row base in B
            unsigned ua[4][4];
            unsigned ubh[4][2], ubl[4][2];
            #pragma unroll
            for (int mt = 0; mt < 4; ++mt) {
                int rm = wm * 64 + mt * 16 + lrow;
                ua[mt][0] = cAhi[(s8 + lk) * SSTR + rm];
                ua[mt][1] = cAhi[(s8 + lk) * SSTR + rm + 8];
                ua[mt][2] = cAhi[(s8 + lk + 4) * SSTR + rm];
                ua[mt][3] = cAhi[(s8 + lk + 4) * SSTR + rm + 8];
            }
            #pragma unroll
            for (int nt = 0; nt < 4; ++nt) {
                int cn = wn * 32 + nt * 8 + lrow;
                ubh[nt][0] = sBhi[(kb + lk) * SSTR + cn];
                ubh[nt][1] = sBhi[(kb + lk + 4) * SSTR + cn];
                ubl[nt][0] = sBlo[(kb + lk) * SSTR + cn];
                ubl[nt][1] = sBlo[(kb + lk + 4) * SSTR + cn];
            }
            // hi x hi
            #pragma unroll
            for (int mt = 0; mt < 4; ++mt)
                #pragma unroll
                for (int nt = 0; nt < 4; ++nt)
                    mma_f16(acc[mt][nt], ua[mt], ubh[nt]);
            // hi x lo
            #pragma unroll
            for (int mt = 0; mt < 4; ++mt)
                #pragma unroll
                for (int nt = 0; nt < 4; ++nt)
                    mma_f16(acc[mt][nt], ua[mt], ubl[nt]);
            // lo x hi
            #pragma unroll
            for (int mt = 0; mt < 4; ++mt) {
                int rm = wm * 64 + mt * 16 + lrow;
                ua[mt][0] = cAlo[(s8 + lk) * SSTR + rm];
                ua[mt][1] = cAlo[(s8 + lk) * SSTR + rm + 8];
                ua[mt][2] = cAlo[(s8 + lk + 4) * SSTR + rm];
                ua[mt][3] = cAlo[(s8 + lk + 4) * SSTR + rm + 8];
            }
            #pragma unroll
            for (int mt = 0; mt < 4; ++mt)
                #pragma unroll
                for (int nt = 0; nt < 4; ++nt)
                    mma_f16(acc[mt][nt], ua[mt], ubh[nt]);
        }

        // split + store prefetched chunk into the other buffer
        if (it < 3) split_store(nAhi, nAlo, v0, v1, v2, v3);
        __syncthreads();
    }

    #pragma unroll
    for (int mt = 0; mt < 4; ++mt) {
        int r0 = rowBase + wm * 64 + mt * 16 + lrow;
        #pragma unroll
        for (int nt = 0; nt < 4; ++nt) {
            int cn = rel * 128 + wn * 32 + nt * 8 + 2 * lk;
            if (r0 < NN)
                *reinterpret_cast<__half2*>(out + (size_t)r0 * 256 + cn) =
                    __floats2half2_rn(acc[mt][nt][0], acc[mt][nt][1]);
            if (r0 + 8 < NN)
                *reinterpret_cast<__half2*>(out + (size_t)(r0 + 8) * 256 + cn) =
                    __floats2half2_rn(acc[mt][nt][2], acc[mt][nt][3]);
        }
    }
}

// ---------------- fused aggregation (CSR gather, fp16 source) ----------------
__device__ __forceinline__ float4 ldh4(const __half* p) {
    uint2 u = *reinterpret_cast<const uint2*>(p);
    float2 fa = __half22float2(*reinterpret_cast<__half2*>(&u.x));
    float2 fb = __half22float2(*reinterpret_cast<__half2*>(&u.y));
    return make_float4(fa.x, fa.y, fb.x, fb.y);
}

__global__ void gather_both(const __half* __restrict__ xw,
                            const float* __restrict__ b_l,
                            float* __restrict__ agg) {
    int t = blockIdx.x * blockDim.x + threadIdx.x;
    int i = t >> 5;
    int lane = t & 31;
    if (i >= NN) return;
    int c4 = lane * 4;

    float s0 = g_invd0[i]; s0 *= s0;
    float s1 = g_invd1[i]; s1 *= s1;
    float4 v0 = ldh4(xw + (size_t)i * 256 + c4);
    float4 v1 = ldh4(xw + (size_t)i * 256 + 128 + c4);
    float4 acc;
    acc.x = fmaf(v0.x, s0, v1.x * s1) + b_l[c4 + 0] + b_l[DD + c4 + 0];
    acc.y = fmaf(v0.y, s0, v1.y * s1) + b_l[c4 + 1] + b_l[DD + c4 + 1];
    acc.z = fmaf(v0.z, s0, v1.z * s1) + b_l[c4 + 2] + b_l[DD + c4 + 2];
    acc.w = fmaf(v0.w, s0, v1.w * s1) + b_l[c4 + 3] + b_l[DD + c4 + 3];

    {
        int b0 = g_ptr0[i], e0 = g_ptr0[i + 1];
        int tt = b0;
        for (; tt + 1 < e0; tt += 2) {
            int2 pA = g_ce0[tt], pB = g_ce0[tt + 1];
            float wA = __int_as_float(pA.y), wB = __int_as_float(pB.y);
            float4 vA = ldh4(xw + (size_t)pA.x * 256 + c4);
            float4 vB = ldh4(xw + (size_t)pB.x * 256 + c4);
            acc.x = fmaf(wA, vA.x, fmaf(wB, vB.x, acc.x));
            acc.y = fmaf(wA, vA.y, fmaf(wB, vB.y, acc.y));
            acc.z = fmaf(wA, vA.z, fmaf(wB, vB.z, acc.z));
            acc.w = fmaf(wA, vA.w, fmaf(wB, vB.w, acc.w));
        }
        if (tt < e0) {
            int2 p = g_ce0[tt];
            float w = __int_as_float(p.y);
            float4 v = ldh4(xw + (size_t)p.x * 256 + c4);
            acc.x = fmaf(w, v.x, acc.x); acc.y = fmaf(w, v.y, acc.y);
            acc.z = fmaf(w, v.z, acc.z); acc.w = fmaf(w, v.w, acc.w);
        }
    }
    {
        int b1 = g_ptr1[i], e1 = g_ptr1[i + 1];
        int tt = b1;
        for (; tt + 1 < e1; tt += 2) {
            int2 pA = g_ce1[tt], pB = g_ce1[tt + 1];
            float wA = __int_as_float(pA.y), wB = __int_as_float(pB.y);
            float4 vA = ldh4(xw + (size_t)pA.x * 256 + 128 + c4);
            float4 vB = ldh4(xw + (size_t)pB.x * 256 + 128 + c4);
            acc.x = fmaf(wA, vA.x, fmaf(wB, vB.x, acc.x));
            acc.y = fmaf(wA, vA.y, fmaf(wB, vB.y, acc.y));
            acc.z = fmaf(wA, vA.z, fmaf(wB, vB.z, acc.z));
            acc.w = fmaf(wA, vA.w, fmaf(wB, vB.w, acc.w));
        }
        if (tt < e1) {
            int2 p = g_ce1[tt];
            float w = __int_as_float(p.y);
            float4 v = ldh4(xw + (size_t)p.x * 256 + 128 + c4);
            acc.x = fmaf(w, v.x, acc.x); acc.y = fmaf(w, v.y, acc.y);
            acc.z = fmaf(w, v.z, acc.z); acc.w = fmaf(w, v.w, acc.w);
        }
    }
    *reinterpret_cast<float4*>(agg + (size_t)i * DD + c4) = acc;
}

// ---------------- pooling + classifier ----------------
__global__ void scan64() {
    if (threadIdx.x == 0) {
        int acc = 0;
        for (int g = 0; g < GG; ++g) { g_offsets[g] = acc; acc += g_counts[g]; }
        g_offsets[GG] = acc;
    }
}

__global__ void pool_partial(const float* __restrict__ h) {
    int g = blockIdx.x;
    int chunk = blockIdx.y;
    int d = threadIdx.x;
    int start = g_offsets[g], end = g_offsets[g + 1];
    int n = end - start;
    int per = (n + (int)gridDim.y - 1) / (int)gridDim.y;
    int s = start + chunk * per;
    int e = min(end, s + per);
    float acc = 0.0f;
    for (int i = s; i < e; ++i) acc += h[(size_t)i * DD + d];
    if (s < e) atomicAdd(&g_pooled[g * DD + d], acc);
}

__global__ void final_linear(const float* __restrict__ lin_w,
                             const float* __restrict__ lin_b,
                             float* __restrict__ out) {
    int t = threadIdx.x;
    int g = t >> 3, c = t & 7;
    float cnt = (float)max(g_counts[g], 1);
    float acc = 0.0f;
    #pragma unroll 16
    for (int d = 0; d < DD; ++d) acc += g_pooled[g * DD + d] * lin_w[d * CC + c];
    out[g * CC + c] = acc / cnt + lin_b[c];
}

// ---------------- launch ----------------
extern "C" void kernel_launch(void* const* d_in, const int* in_sizes, int n_in,
                              void* d_out, int out_size) {
    const float* x     = (const float*)d_in[0];
    const float* W     = (const float*)d_in[1];
    const float* b     = (const float*)d_in[2];
    const float* lin_w = (const float*)d_in[3];
    const float* lin_b = (const float*)d_in[4];
    const int*   ei    = (const int*)d_in[5];
    const int*   batch = (const int*)d_in[6];
    float* out = (float*)d_out;

    __half* xw; float* agg;
    unsigned *whi, *wlo;
    cudaGetSymbolAddress((void**)&xw,  g_xw);
    cudaGetSymbolAddress((void**)&agg, g_agg);
    cudaGetSymbolAddress((void**)&whi, g_whi);
    cudaGetSymbolAddress((void**)&wlo, g_wlo);

    cudaFuncSetAttribute(gemm_tc<false>, cudaFuncAttributeMaxDynamicSharedMemorySize,
                         GEMM_SMEM_BYTES);
    cudaFuncSetAttribute(gemm_tc<true>, cudaFuncAttributeMaxDynamicSharedMemorySize,
                         GEMM_SMEM_BYTES);

    const int TB = 256;
    int histBlocks  = (2 * EE + NN + TB - 1) / TB;
    int edge2Blocks = (2 * EE + TB - 1) / TB;
    int warpBlocks  = (NN * 32 + TB - 1) / TB;
    dim3 gemmGrid((NN + 127) / 128, 2);
    dim3 scanGrid(SCAN_BLOCKS, 2);

    const int WMAT = (DD / 2) * DD;   // packed uints per weight matrix

    zero_wsplit<<<256, TB>>>(W);                    // 0
    hist_both<<<histBlocks, TB>>>(ei, batch);       // 1
    scan_p1<<<scanGrid, SCAN_TB>>>();               // 2
    gemm_tc<false><<<gemmGrid, 256, GEMM_SMEM_BYTES>>>(x, whi, wlo, xw);   // 3 (profiled)
    scan_p2<<<2, 256>>>();                          // 4
    scan_p3<<<scanGrid, SCAN_TB>>>();               // 5
    csr_fill_both<<<edge2Blocks, TB>>>(ei);         // 6
    gather_both<<<warpBlocks, TB>>>(xw, b + 0 * 2 * DD, agg);              // 7

    gemm_tc<true><<<gemmGrid, 256, GEMM_SMEM_BYTES>>>(agg, whi + 2 * WMAT,
                                                      wlo + 2 * WMAT, xw); // 8
    gather_both<<<warpBlocks, TB>>>(xw, b + 1 * 2 * DD, agg);              // 9

    scan64<<<1, 32>>>();
    dim3 pg(GG, 8);
    pool_partial<<<pg, DD>>>(agg);
    final_linear<<<1, GG * CC>>>(lin_w, lin_b, out);
}

// round 14
// speedup vs baseline: 1.3816x; 1.0406x over previous
#include <cuda_runtime.h>
#include <cuda_fp16.h>

#define NN 50000
#define EE 800000
#define DD 128
#define GG 64
#define CC 8

#define SCAN_TB 256
#define SCAN_BLOCKS ((NN + SCAN_TB - 1) / SCAN_TB)   // 196

#define SSTR 136
// B hi/lo resident (2*64 rows) + A hi/lo double-buffer (2*2*8 rows)
#define GEMM_SMEM_UINTS ((64 * 2 + 2 * 2 * 8) * SSTR)
#define GEMM_SMEM_BYTES (GEMM_SMEM_UINTS * 4)        // 87040

// ---------------- static scratch ----------------
__device__ __half g_xw[NN * 256];       // [N, 256] fp16: cols 0-127 rel0, 128-255 rel1
__device__ float g_agg[NN * DD];
__device__ float g_invd0[NN];
__device__ float g_invd1[NN];
__device__ int   g_deg0[NN];
__device__ int   g_deg1[NN];
__device__ int   g_ptr0[NN + 1];
__device__ int   g_ptr1[NN + 1];
__device__ int   g_cur0[NN];
__device__ int   g_cur1[NN];
__device__ int2  g_ce0[EE];
__device__ int2  g_ce1[EE];
__device__ int   g_bsum[2][SCAN_BLOCKS];
// pre-split W as packed fp16 pairs: [mat(layer*2+rel)][k2 (=k/2)][c], uint = {half(k), half(k+1)}
__device__ unsigned g_whi[2 * 2 * (DD / 2) * DD];
__device__ unsigned g_wlo[2 * 2 * (DD / 2) * DD];
__device__ float g_pooled[GG * DD];
__device__ int   g_counts[GG];
__device__ int   g_offsets[GG + 1];

// ---------------- helpers ----------------
__device__ __forceinline__ void pdl_trigger() {
    asm volatile("griddepcontrol.launch_dependents;");
}
__device__ __forceinline__ void pdl_wait() {
    asm volatile("griddepcontrol.wait;");
}
__device__ __forceinline__ unsigned packh2(__half a, __half b) {
    __half2 h = __halves2half2(a, b);
    return *reinterpret_cast<unsigned*>(&h);
}
__device__ __forceinline__ void mma_f16(float* c, const unsigned* a, const unsigned* b) {
    asm volatile(
        "mma.sync.aligned.m16n8k16.row.col.f32.f16.f16.f32 "
        "{%0,%1,%2,%3}, {%4,%5,%6,%7}, {%8,%9}, {%0,%1,%2,%3};"
        : "+f"(c[0]), "+f"(c[1]), "+f"(c[2]), "+f"(c[3])
        : "r"(a[0]), "r"(a[1]), "r"(a[2]), "r"(a[3]), "r"(b[0]), "r"(b[1]));
}

// ---------------- setup ----------------
// zero counters + split W into fp16 hi/lo pairs (both dependency-free)
__global__ void zero_wsplit(const float* __restrict__ W) {
    int i = blockIdx.x * blockDim.x + threadIdx.x;   // 256*256 = 65536 threads
    if (i < NN) { g_deg0[i] = 0; g_deg1[i] = 0; }
    if (i < GG) g_counts[i] = 0;
    if (i < GG * DD) g_pooled[i] = 0.0f;
    if (i < 2 * 2 * (DD / 2) * DD) {
        int mat = i / ((DD / 2) * DD);
        int rem = i % ((DD / 2) * DD);
        int k2 = rem / DD, c = rem % DD;
        const float* Wm = W + mat * DD * DD;
        float w0 = Wm[(2 * k2) * DD + c];
        float w1 = Wm[(2 * k2 + 1) * DD + c];
        __half h0 = __float2half_rn(w0);
        __half h1 = __float2half_rn(w1);
        __half l0 = __float2half_rn(w0 - __half2float(h0));
        __half l1 = __float2half_rn(w1 - __half2float(h1));
        g_whi[i] = packh2(h0, h1);
        g_wlo[i] = packh2(l0, l1);
    }
}

// degree histograms for both relations + batch counts, one kernel.
// Launched with PDL after gemm0 (independent of it: touches deg/counts only).
__global__ void hist_both(const int* __restrict__ ei, const int* __restrict__ batch) {
    pdl_trigger();
    int t = blockIdx.x * blockDim.x + threadIdx.x;
    if (t < EE)                 atomicAdd(&g_deg0[ei[EE + t]], 1);
    else if (t < 2 * EE)        atomicAdd(&g_deg1[ei[3 * EE + (t - EE)]], 1);
    else if (t < 2 * EE + NN)   atomicAdd(&g_counts[batch[t - 2 * EE]], 1);
}

// block-exclusive prescan; also computes invd (fused). Depends on hist -> pdl_wait.
__global__ void scan_p1() {
    pdl_trigger();
    pdl_wait();
    int rel = blockIdx.y;
    const int* __restrict__ cnt = rel ? g_deg1 : g_deg0;
    int* __restrict__ ptr = rel ? g_ptr1 : g_ptr0;
    float* __restrict__ invd = rel ? g_invd1 : g_invd0;
    int i = blockIdx.x * SCAN_TB + threadIdx.x;
    int v = (i < NN) ? cnt[i] : 0;
    if (i < NN) invd[i] = rsqrtf((float)(v + 1));
    int lane = threadIdx.x & 31, w = threadIdx.x >> 5;
    int incl = v;
    #pragma unroll
    for (int o = 1; o < 32; o <<= 1) {
        int t = __shfl_up_sync(0xffffffffu, incl, o);
        if (lane >= o) incl += t;
    }
    __shared__ int wsum[8];
    if (lane == 31) wsum[w] = incl;
    __syncthreads();
    if (w == 0) {
        int s = (lane < 8) ? wsum[lane] : 0;
        #pragma unroll
        for (int o = 1; o < 8; o <<= 1) {
            int t = __shfl_up_sync(0xffffffffu, s, o);
            if (lane >= o) s += t;
        }
        if (lane < 8) wsum[lane] = s;
    }
    __syncthreads();
    int base = (w > 0) ? wsum[w - 1] : 0;
    if (i < NN) ptr[i] = base + incl - v;
    if (threadIdx.x == SCAN_TB - 1) g_bsum[rel][blockIdx.x] = base + incl;
}

__global__ void scan_p2() {
    pdl_trigger();
    pdl_wait();
    int rel = blockIdx.x;
    int tid = threadIdx.x;
    int v = (tid < SCAN_BLOCKS) ? g_bsum[rel][tid] : 0;
    int lane = tid & 31, w = tid >> 5;
    int incl = v;
    #pragma unroll
    for (int o = 1; o < 32; o <<= 1) {
        int t = __shfl_up_sync(0xffffffffu, incl, o);
        if (lane >= o) incl += t;
    }
    __shared__ int wsum[8];
    if (lane == 31) wsum[w] = incl;
    __syncthreads();
    if (w == 0) {
        int s = (lane < 8) ? wsum[lane] : 0;
        #pragma unroll
        for (int o = 1; o < 8; o <<= 1) {
            int t = __shfl_up_sync(0xffffffffu, s, o);
            if (lane >= o) s += t;
        }
        if (lane < 8) wsum[lane] = s;
    }
    __syncthreads();
    int base = (w > 0) ? wsum[w - 1] : 0;
    if (tid < SCAN_BLOCKS) g_bsum[rel][tid] = base + incl - v;
}

__global__ void scan_p3() {
    pdl_trigger();
    pdl_wait();
    int rel = blockIdx.y;
    int* __restrict__ ptr = rel ? g_ptr1 : g_ptr0;
    int* __restrict__ cur = rel ? g_cur1 : g_cur0;
    int i = blockIdx.x * SCAN_TB + threadIdx.x;
    if (i < NN) {
        int p = ptr[i] + g_bsum[rel][blockIdx.x];
        ptr[i] = p; cur[i] = p;
    }
    if (i == 0) ptr[NN] = EE;
}

__global__ void csr_fill_both(const int* __restrict__ ei) {
    pdl_wait();
    int t = blockIdx.x * blockDim.x + threadIdx.x;
    if (t < EE) {
        int s = ei[t], d = ei[EE + t];
        int slot = atomicAdd(&g_cur0[d], 1);
        int2 p; p.x = s; p.y = __float_as_int(g_invd0[s] * g_invd0[d]);
        g_ce0[slot] = p;
    } else if (t < 2 * EE) {
        int e = t - EE;
        int s = ei[2 * EE + e], d = ei[3 * EE + e];
        int slot = atomicAdd(&g_cur1[d], 1);
        int2 p; p.x = s; p.y = __float_as_int(g_invd1[s] * g_invd1[d]);
        g_ce1[slot] = p;
    }
}

// ---------------- tensor-core GEMM (round-10: 3-term fp16 split, B resident, A double-buffered, BK=16) ----------------
// 256 threads, grid (391, 2). One __syncthreads per 16-K chunk.
template <bool RELU>
__global__ void __launch_bounds__(256, 2)
gemm_tc(const float* __restrict__ A, const unsigned* __restrict__ Whi,
        const unsigned* __restrict__ Wlo, __half* __restrict__ out) {
    pdl_trigger();    // lets the (independent) setup chain launch behind layer-0
    extern __shared__ unsigned dynsm[];
    unsigned* sBhi = dynsm;                       // [64][SSTR]
    unsigned* sBlo = sBhi + 64 * SSTR;            // [64][SSTR]
    unsigned* sAhi = sBlo + 64 * SSTR;            // [2][8][SSTR]
    unsigned* sAlo = sAhi + 2 * 8 * SSTR;         // [2][8][SSTR]

    const int rel = blockIdx.y;
    const unsigned* Bh = Whi + rel * (DD / 2) * DD;
    const unsigned* Bl = Wlo + rel * (DD / 2) * DD;
    const int rowBase = blockIdx.x * 128;
    const int tid = threadIdx.x;
    const int warp = tid >> 5, lane = tid & 31;
    const int wm = warp >> 2, wn = warp & 3;
    const int lrow = lane >> 2;     // 0..7
    const int lk = lane & 3;        // pair index 0..3

    float acc[4][4][4];
    #pragma unroll
    for (int i = 0; i < 4; ++i)
        #pragma unroll
        for (int j = 0; j < 4; ++j)
            #pragma unroll
            for (int q = 0; q < 4; ++q) acc[i][j][q] = 0.0f;

    // ---- load whole B (hi+lo) into smem once ----
    #pragma unroll
    for (int i = 0; i < 8; ++i) {
        int idx = tid + i * 256;               // 0..2047 uint4 slots
        int k2 = idx >> 5, c = (idx & 31) * 4;
        *reinterpret_cast<uint4*>(&sBhi[k2 * SSTR + c]) =
            *reinterpret_cast<const uint4*>(Bh + k2 * DD + c);
        *reinterpret_cast<uint4*>(&sBlo[k2 * SSTR + c]) =
            *reinterpret_cast<const uint4*>(Bl + k2 * DD + c);
    }

    const int alr = tid >> 1;            // A row 0..127
    const int alk = (tid & 1) * 8;       // k offset 0 or 8
    const int ap2 = (tid & 1) * 4;       // pair-row offset 0 or 4
    const int agr = rowBase + alr;
    const bool arow_ok = (agr < NN);
    const float* aBase = A + (size_t)agr * DD + alk;

    // ---- prologue: load + split chunk 0 into buffer 0 ----
    {
        float4 v0 = make_float4(0.f, 0.f, 0.f, 0.f), v1 = v0;
        if (arow_ok) {
            v0 = *reinterpret_cast<const float4*>(aBase);
            v1 = *reinterpret_cast<const float4*>(aBase + 4);
        }
        if (RELU) {
            v0.x = fmaxf(v0.x, 0.f); v0.y = fmaxf(v0.y, 0.f);
            v0.z = fmaxf(v0.z, 0.f); v0.w = fmaxf(v0.w, 0.f);
            v1.x = fmaxf(v1.x, 0.f); v1.y = fmaxf(v1.y, 0.f);
            v1.z = fmaxf(v1.z, 0.f); v1.w = fmaxf(v1.w, 0.f);
        }
        float va[8] = {v0.x, v0.y, v0.z, v0.w, v1.x, v1.y, v1.z, v1.w};
        #pragma unroll
        for (int p = 0; p < 4; ++p) {
            __half h0 = __float2half_rn(va[2 * p]);
            __half h1 = __float2half_rn(va[2 * p + 1]);
            __half l0 = __float2half_rn(va[2 * p] - __half2float(h0));
            __half l1 = __float2half_rn(va[2 * p + 1] - __half2float(h1));
            sAhi[(ap2 + p) * SSTR + alr] = packh2(h0, h1);
            sAlo[(ap2 + p) * SSTR + alr] = packh2(l0, l1);
        }
    }
    __syncthreads();

    // ---- mainloop: 8 chunks, prefetch next A while computing ----
    #pragma unroll
    for (int c = 0; c < 8; ++c) {
        const int cur = c & 1;
        unsigned* cAhi = sAhi + cur * 8 * SSTR;
        unsigned* cAlo = sAlo + cur * 8 * SSTR;
        unsigned* nAhi = sAhi + (cur ^ 1) * 8 * SSTR;
        unsigned* nAlo = sAlo + (cur ^ 1) * 8 * SSTR;

        // prefetch next chunk (LDG issued before LDS/MMA)
        float4 v0 = make_float4(0.f, 0.f, 0.f, 0.f), v1 = v0;
        if (c < 7 && arow_ok) {
            const float* ap = aBase + (c + 1) * 16;
            v0 = *reinterpret_cast<const float4*>(ap);
            v1 = *reinterpret_cast<const float4*>(ap + 4);
        }

        // fragments
        const int kb = c * 8;
        unsigned ua[4][4];
        unsigned ubh[4][2], ubl[4][2];
        #pragma unroll
        for (int mt = 0; mt < 4; ++mt) {
            int rm = wm * 64 + mt * 16 + lrow;
            ua[mt][0] = cAhi[lk * SSTR + rm];
            ua[mt][1] = cAhi[lk * SSTR + rm + 8];
            ua[mt][2] = cAhi[(lk + 4) * SSTR + rm];
            ua[mt][3] = cAhi[(lk + 4) * SSTR + rm + 8];
        }
        #pragma unroll
        for (int nt = 0; nt < 4; ++nt) {
            int cn = wn * 32 + nt * 8 + lrow;
            ubh[nt][0] = sBhi[(kb + lk) * SSTR + cn];
            ubh[nt][1] = sBhi[(kb + lk + 4) * SSTR + cn];
            ubl[nt][0] = sBlo[(kb + lk) * SSTR + cn];
            ubl[nt][1] = sBlo[(kb + lk + 4) * SSTR + cn];
        }
        // hi x hi
        #pragma unroll
        for (int mt = 0; mt < 4; ++mt)
            #pragma unroll
            for (int nt = 0; nt < 4; ++nt)
                mma_f16(acc[mt][nt], ua[mt], ubh[nt]);
        // hi x lo
        #pragma unroll
        for (int mt = 0; mt < 4; ++mt)
            #pragma unroll
            for (int nt = 0; nt < 4; ++nt)
                mma_f16(acc[mt][nt], ua[mt], ubl[nt]);
        // lo x hi
        #pragma unroll
        for (int mt = 0; mt < 4; ++mt) {
            int rm = wm * 64 + mt * 16 + lrow;
            ua[mt][0] = cAlo[lk * SSTR + rm];
            ua[mt][1] = cAlo[lk * SSTR + rm + 8];
            ua[mt][2] = cAlo[(lk + 4) * SSTR + rm];
            ua[mt][3] = cAlo[(lk + 4) * SSTR + rm + 8];
        }
        #pragma unroll
        for (int mt = 0; mt < 4; ++mt)
            #pragma unroll
            for (int nt = 0; nt < 4; ++nt)
                mma_f16(acc[mt][nt], ua[mt], ubh[nt]);

        // split + store prefetched chunk into the other buffer
        if (c < 7) {
            if (RELU) {
                v0.x = fmaxf(v0.x, 0.f); v0.y = fmaxf(v0.y, 0.f);
                v0.z = fmaxf(v0.z, 0.f); v0.w = fmaxf(v0.w, 0.f);
                v1.x = fmaxf(v1.x, 0.f); v1.y = fmaxf(v1.y, 0.f);
                v1.z = fmaxf(v1.z, 0.f); v1.w = fmaxf(v1.w, 0.f);
            }
            float va[8] = {v0.x, v0.y, v0.z, v0.w, v1.x, v1.y, v1.z, v1.w};
            #pragma unroll
            for (int p = 0; p < 4; ++p) {
                __half h0 = __float2half_rn(va[2 * p]);
                __half h1 = __float2half_rn(va[2 * p + 1]);
                __half l0 = __float2half_rn(va[2 * p] - __half2float(h0));
                __half l1 = __float2half_rn(va[2 * p + 1] - __half2float(h1));
                nAhi[(ap2 + p) * SSTR + alr] = packh2(h0, h1);
                nAlo[(ap2 + p) * SSTR + alr] = packh2(l0, l1);
            }
        }
        __syncthreads();
    }

    #pragma unroll
    for (int mt = 0; mt < 4; ++mt) {
        int r0 = rowBase + wm * 64 + mt * 16 + lrow;
        #pragma unroll
        for (int nt = 0; nt < 4; ++nt) {
            int cn = rel * 128 + wn * 32 + nt * 8 + 2 * lk;
            if (r0 < NN)
                *reinterpret_cast<__half2*>(out + (size_t)r0 * 256 + cn) =
                    __floats2half2_rn(acc[mt][nt][0], acc[mt][nt][1]);
            if (r0 + 8 < NN)
                *reinterpret_cast<__half2*>(out + (size_t)(r0 + 8) * 256 + cn) =
                    __floats2half2_rn(acc[mt][nt][2], acc[mt][nt][3]);
        }
    }
}

// ---------------- fused aggregation (CSR gather, fp16 source) ----------------
__device__ __forceinline__ float4 ldh4(const __half* p) {
    uint2 u = *reinterpret_cast<const uint2*>(p);
    float2 fa = __half22float2(*reinterpret_cast<__half2*>(&u.x));
    float2 fb = __half22float2(*reinterpret_cast<__half2*>(&u.y));
    return make_float4(fa.x, fa.y, fb.x, fb.y);
}

__global__ void gather_both(const __half* __restrict__ xw,
                            const float* __restrict__ b_l,
                            float* __restrict__ agg) {
    int t = blockIdx.x * blockDim.x + threadIdx.x;
    int i = t >> 5;
    int lane = t & 31;
    if (i >= NN) return;
    int c4 = lane * 4;

    float s0 = g_invd0[i]; s0 *= s0;
    float s1 = g_invd1[i]; s1 *= s1;
    float4 v0 = ldh4(xw + (size_t)i * 256 + c4);
    float4 v1 = ldh4(xw + (size_t)i * 256 + 128 + c4);
    float4 acc;
    acc.x = fmaf(v0.x, s0, v1.x * s1) + b_l[c4 + 0] + b_l[DD + c4 + 0];
    acc.y = fmaf(v0.y, s0, v1.y * s1) + b_l[c4 + 1] + b_l[DD + c4 + 1];
    acc.z = fmaf(v0.z, s0, v1.z * s1) + b_l[c4 + 2] + b_l[DD + c4 + 2];
    acc.w = fmaf(v0.w, s0, v1.w * s1) + b_l[c4 + 3] + b_l[DD + c4 + 3];

    {
        int b0 = g_ptr0[i], e0 = g_ptr0[i + 1];
        int tt = b0;
        for (; tt + 1 < e0; tt += 2) {
            int2 pA = g_ce0[tt], pB = g_ce0[tt + 1];
            float wA = __int_as_float(pA.y), wB = __int_as_float(pB.y);
            float4 vA = ldh4(xw + (size_t)pA.x * 256 + c4);
            float4 vB = ldh4(xw + (size_t)pB.x * 256 + c4);
            acc.x = fmaf(wA, vA.x, fmaf(wB, vB.x, acc.x));
            acc.y = fmaf(wA, vA.y, fmaf(wB, vB.y, acc.y));
            acc.z = fmaf(wA, vA.z, fmaf(wB, vB.z, acc.z));
            acc.w = fmaf(wA, vA.w, fmaf(wB, vB.w, acc.w));
        }
        if (tt < e0) {
            int2 p = g_ce0[tt];
            float w = __int_as_float(p.y);
            float4 v = ldh4(xw + (size_t)p.x * 256 + c4);
            acc.x = fmaf(w, v.x, acc.x); acc.y = fmaf(w, v.y, acc.y);
            acc.z = fmaf(w, v.z, acc.z); acc.w = fmaf(w, v.w, acc.w);
        }
    }
    {
        int b1 = g_ptr1[i], e1 = g_ptr1[i + 1];
        int tt = b1;
        for (; tt + 1 < e1; tt += 2) {
            int2 pA = g_ce1[tt], pB = g_ce1[tt + 1];
            float wA = __int_as_float(pA.y), wB = __int_as_float(pB.y);
            float4 vA = ldh4(xw + (size_t)pA.x * 256 + 128 + c4);
            float4 vB = ldh4(xw + (size_t)pB.x * 256 + 128 + c4);
            acc.x = fmaf(wA, vA.x, fmaf(wB, vB.x, acc.x));
            acc.y = fmaf(wA, vA.y, fmaf(wB, vB.y, acc.y));
            acc.z = fmaf(wA, vA.z, fmaf(wB, vB.z, acc.z));
            acc.w = fmaf(wA, vA.w, fmaf(wB, vB.w, acc.w));
        }
        if (tt < e1) {
            int2 p = g_ce1[tt];
            float w = __int_as_float(p.y);
            float4 v = ldh4(xw + (size_t)p.x * 256 + 128 + c4);
            acc.x = fmaf(w, v.x, acc.x); acc.y = fmaf(w, v.y, acc.y);
            acc.z = fmaf(w, v.z, acc.z); acc.w = fmaf(w, v.w, acc.w);
        }
    }
    *reinterpret_cast<float4*>(agg + (size_t)i * DD + c4) = acc;
}

// ---------------- pooling + classifier ----------------
__global__ void scan64() {
    if (threadIdx.x == 0) {
        int acc = 0;
        for (int g = 0; g < GG; ++g) { g_offsets[g] = acc; acc += g_counts[g]; }
        g_offsets[GG] = acc;
    }
}

__global__ void pool_partial(const float* __restrict__ h) {
    int g = blockIdx.x;
    int chunk = blockIdx.y;
    int d = threadIdx.x;
    int start = g_offsets[g], end = g_offsets[g + 1];
    int n = end - start;
    int per = (n + (int)gridDim.y - 1) / (int)gridDim.y;
    int s = start + chunk * per;
    int e = min(end, s + per);
    float acc = 0.0f;
    for (int i = s; i < e; ++i) acc += h[(size_t)i * DD + d];
    if (s < e) atomicAdd(&g_pooled[g * DD + d], acc);
}

__global__ void final_linear(const float* __restrict__ lin_w,
                             const float* __restrict__ lin_b,
                             float* __restrict__ out) {
    int t = threadIdx.x;
    int g = t >> 3, c = t & 7;
    float cnt = (float)max(g_counts[g], 1);
    float acc = 0.0f;
    #pragma unroll 16
    for (int d = 0; d < DD; ++d) acc += g_pooled[g * DD + d] * lin_w[d * CC + c];
    out[g * CC + c] = acc / cnt + lin_b[c];
}

// ---------------- launch ----------------
extern "C" void kernel_launch(void* const* d_in, const int* in_sizes, int n_in,
                              void* d_out, int out_size) {
    const float* x     = (const float*)d_in[0];
    const float* W     = (const float*)d_in[1];
    const float* b     = (const float*)d_in[2];
    const float* lin_w = (const float*)d_in[3];
    const float* lin_b = (const float*)d_in[4];
    const int*   ei    = (const int*)d_in[5];
    const int*   batch = (const int*)d_in[6];
    float* out = (float*)d_out;

    __half* xw; float* agg;
    unsigned *whi, *wlo;
    cudaGetSymbolAddress((void**)&xw,  g_xw);
    cudaGetSymbolAddress((void**)&agg, g_agg);
    cudaGetSymbolAddress((void**)&whi, g_whi);
    cudaGetSymbolAddress((void**)&wlo, g_wlo);

    cudaFuncSetAttribute(gemm_tc<false>, cudaFuncAttributeMaxDynamicSharedMemorySize,
                         GEMM_SMEM_BYTES);
    cudaFuncSetAttribute(gemm_tc<true>, cudaFuncAttributeMaxDynamicSharedMemorySize,
                         GEMM_SMEM_BYTES);

    const int TB = 256;
    int histBlocks  = (2 * EE + NN + TB - 1) / TB;
    int edge2Blocks = (2 * EE + TB - 1) / TB;
    int warpBlocks  = (NN * 32 + TB - 1) / TB;
    dim3 gemmGrid((NN + 127) / 128, 2);
    dim3 scanGrid(SCAN_BLOCKS, 2);

    const int WMAT = (DD / 2) * DD;   // packed uints per weight matrix

    // PDL launch attribute (programmatic stream serialization)
    cudaLaunchAttribute pdlAttr[1];
    pdlAttr[0].id = cudaLaunchAttributeProgrammaticStreamSerialization;
    pdlAttr[0].val.programmaticStreamSerializationAllowed = 1;

    // 0: zero + wsplit (normal)
    zero_wsplit<<<256, TB>>>(W);

    // 1: layer-0 GEMM (normal; triggers dependents early)
    gemm_tc<false><<<gemmGrid, 256, GEMM_SMEM_BYTES>>>(x, whi, wlo, xw);

    // 2-6: setup chain with PDL — overlaps with gemm0's tail; internal deps use griddepcontrol.wait
    {
        cudaLaunchConfig_t cfg = {};
        cfg.blockDim = dim3(TB, 1, 1);
        cfg.attrs = pdlAttr;
        cfg.numAttrs = 1;
        cfg.stream = 0;

        cfg.gridDim = dim3(histBlocks, 1, 1);
        cudaLaunchKernelEx(&cfg, hist_both, ei, batch);

        cfg.gridDim = scanGrid;
        cudaLaunchKernelEx(&cfg, scan_p1);

        cfg.gridDim = dim3(2, 1, 1);
        cudaLaunchKernelEx(&cfg, scan_p2);

        cfg.gridDim = scanGrid;
        cudaLaunchKernelEx(&cfg, scan_p3);

        cfg.gridDim = dim3(edge2Blocks, 1, 1);
        cudaLaunchKernelEx(&cfg, csr_fill_both, ei);
    }

    // 7: gather L0 (normal: waits for gemm0 AND csr_fill)
    gather_both<<<warpBlocks, TB>>>(xw, b + 0 * 2 * DD, agg);

    // 8-9: layer 1
    gemm_tc<true><<<gemmGrid, 256, GEMM_SMEM_BYTES>>>(agg, whi + 2 * WMAT,
                                                      wlo + 2 * WMAT, xw);
    gather_both<<<warpBlocks, TB>>>(xw, b + 1 * 2 * DD, agg);

    // pooling + classifier
    scan64<<<1, 32>>>();
    dim3 pg(GG, 8);
    pool_partial<<<pg, DD>>>(agg);
    final_linear<<<1, GG * CC>>>(lin_w, lin_b, out);
}